// round 5
// baseline (speedup 1.0000x reference)
#include <cuda_runtime.h>
#include <cuda_fp16.h>
#include <mma.h>
#include <math.h>

using namespace nvcuda;

#define B 2
#define S 2048
#define D 512
#define H 8
#define DH 64
#define NB 10
#define PI_F 3.14159265358979323846f

// ---------------- scratch ----------------------------------------------------
__device__ float g_qp[B*S*D];
__device__ float g_kp[B*S*D];
__device__ float g_vp[B*S*D];
__device__ float g_coef[NB*B*H*S];                 // [n][b][h][s], pre-scaled by 0.1/8
__device__ float g_logits[(size_t)B*H*S*S];        // 268 MB
__device__ float g_attnv[B*S*D];                   // attn @ V, (b,s, h*64+d)

// ---------------- tf32 wmma GEMM:  C = A(MxK) @ W(KxN) + bias ----------------
#define GT_ALD 36
#define GT_WLD 132
__global__ __launch_bounds__(256) void gemm_bias_tc(
    const float* __restrict__ A, const float* __restrict__ W,
    const float* __restrict__ bias, float* __restrict__ C,
    int M, int N, int K)
{
    __shared__ float As[128*GT_ALD];   // [m][k]
    __shared__ float Ws[32*GT_WLD];    // [k][n]
    __shared__ float Bt[16*GT_WLD];    // bias tile (rows identical)
    const int bm = blockIdx.y * 128, bn = blockIdx.x * 128;
    const int tid = threadIdx.x, w = tid >> 5;
    const int wm = (w >> 1) * 32, wn = (w & 1) * 64;

    for (int i = tid; i < 16*128; i += 256) {
        int r = i >> 7, c = i & 127;
        Bt[r*GT_WLD + c] = bias[bn + c];
    }
    __syncthreads();

    wmma::fragment<wmma::accumulator, 16,16,8, float> acc[2][4];
    #pragma unroll
    for (int i = 0; i < 2; i++)
        #pragma unroll
        for (int j = 0; j < 4; j++)
            wmma::load_matrix_sync(acc[i][j], Bt + wn + j*16, GT_WLD, wmma::mem_row_major);

    for (int k0 = 0; k0 < K; k0 += 32) {
        #pragma unroll
        for (int i = 0; i < 4; i++) {
            int id = i*256 + tid;
            int row = id >> 3, kc = (id & 7) * 4;
            float4 v = *(const float4*)&A[(size_t)(bm + row) * K + k0 + kc];
            *(float4*)&As[row*GT_ALD + kc] = v;
        }
        #pragma unroll
        for (int i = 0; i < 4; i++) {
            int id = i*256 + tid;
            int kr = id >> 5, nc = (id & 31) * 4;
            float4 v = *(const float4*)&W[(size_t)(k0 + kr) * N + bn + nc];
            *(float4*)&Ws[kr*GT_WLD + nc] = v;
        }
        __syncthreads();
        #pragma unroll
        for (int ks = 0; ks < 4; ks++) {
            wmma::fragment<wmma::matrix_a, 16,16,8, wmma::precision::tf32, wmma::row_major> a0, a1;
            wmma::load_matrix_sync(a0, As + wm*GT_ALD + ks*8, GT_ALD);
            wmma::load_matrix_sync(a1, As + (wm+16)*GT_ALD + ks*8, GT_ALD);
            #pragma unroll
            for (int i = 0; i < a0.num_elements; i++) {
                a0.x[i] = wmma::__float_to_tf32(a0.x[i]);
                a1.x[i] = wmma::__float_to_tf32(a1.x[i]);
            }
            #pragma unroll
            for (int j = 0; j < 4; j++) {
                wmma::fragment<wmma::matrix_b, 16,16,8, wmma::precision::tf32, wmma::row_major> bf;
                wmma::load_matrix_sync(bf, Ws + (ks*8)*GT_WLD + wn + j*16, GT_WLD);
                #pragma unroll
                for (int i = 0; i < bf.num_elements; i++) bf.x[i] = wmma::__float_to_tf32(bf.x[i]);
                wmma::mma_sync(acc[0][j], a0, bf, acc[0][j]);
                wmma::mma_sync(acc[1][j], a1, bf, acc[1][j]);
            }
        }
        __syncthreads();
    }
    #pragma unroll
    for (int i = 0; i < 2; i++)
        #pragma unroll
        for (int j = 0; j < 4; j++)
            wmma::store_matrix_sync(C + (size_t)(bm + wm + i*16) * N + bn + wn + j*16,
                                    acc[i][j], N, wmma::mem_row_major);
}

// ---------------- coef: (B*S x 512) @ (512 x 80) ------------------------------
__global__ void coef_kernel(const float* __restrict__ Wcoef, const float* __restrict__ bcoef)
{
    __shared__ float qsm[16*33];
    __shared__ float wsm[32*80];
    const int bm = blockIdx.x * 16;
    const int t = threadIdx.x;
    const int r = t & 15;             // row within tile
    const int cg = t >> 4;            // col group: 5 cols each (16 groups)
    float acc[5] = {};
    for (int k0 = 0; k0 < D; k0 += 32) {
        #pragma unroll
        for (int i = 0; i < 2; i++) {
            int idx = i*256 + t;
            int rr = idx >> 5, cc = idx & 31;
            qsm[rr*33 + cc] = g_qp[(size_t)(bm + rr) * D + k0 + cc];
        }
        #pragma unroll
        for (int i = 0; i < 10; i++) {
            int idx = i*256 + t;
            int kk = idx / 80, nh = idx % 80;
            wsm[kk*80 + nh] = Wcoef[(size_t)(nh >> 3) * D * H + (size_t)(k0 + kk) * H + (nh & 7)];
        }
        __syncthreads();
        #pragma unroll 8
        for (int kk = 0; kk < 32; kk++) {
            float a = qsm[r*33 + kk];
            #pragma unroll
            for (int j = 0; j < 5; j++)
                acc[j] += a * wsm[kk*80 + cg*5 + j];
        }
        __syncthreads();
    }
    const int rg = bm + r;
    const int b = rg >> 11, s = rg & (S-1);
    #pragma unroll
    for (int j = 0; j < 5; j++) {
        int nh = cg*5 + j;
        int n = nh >> 3, h = nh & 7;
        float v = acc[j] + bcoef[nh];
        if (n == 1) v = fabsf(v);
        g_coef[(((size_t)n*B + b)*H + h)*S + s] = 0.0125f * v;   // 0.1 / sqrt(64)
    }
}

// ---------------- fused basis + coef-dot + QK^T (wmma tf32, half2 epilogue) --
// Ladder (s/c of pi x, 3pi x, 5pi x, 9pi x) computed ONCE per cell in packed
// half2 and kept in registers; per head only the 10-term dot runs (half2 fma).
#define QK_LD  68
#define LG_SMEM ((3*64*QK_LD + NB*64) * 4)
__global__ __launch_bounds__(256, 2) void logits_kernel(const float* __restrict__ xdiff)
{
    extern __shared__ float sm[];
    float* qs  = sm;                          // 64*68 (pre-scaled by 0.125)
    float* ks  = qs + 64*QK_LD;               // 64*68
    float* ct  = ks + 64*QK_LD;               // 64*68 basis-init / C tile
    float* cf  = ct + 64*QK_LD;               // 10*64

    const int b = blockIdx.z;
    const int q0 = blockIdx.y * 64, k0 = blockIdx.x * 64;
    const int tid = threadIdx.x;
    const int w = tid >> 5;
    const int wr = w >> 1, wc = w & 1;        // 4x2 warp grid over 64x64

    // each thread owns 16 cells: row dq, k strip of 16 (= 8 half2 pairs)
    const int dq = tid >> 2;
    const int dk = (tid & 3) * 16;

    half2 XH[8], S1[8], C1[8], S3[8], C3[8], S5[8], C5[8], S9[8], C9[8];
    {
        float xs[16], ss[16], cs[16];
        const float* xp = &xdiff[((size_t)b*S + q0 + dq) * S + k0 + dk];
        #pragma unroll
        for (int j4 = 0; j4 < 4; j4++) {
            float4 x4 = *(const float4*)&xp[j4*4];
            float xv[4] = {x4.x, x4.y, x4.z, x4.w};
            #pragma unroll
            for (int u = 0; u < 4; u++) {
                int j = j4*4 + u;
                float x = xv[u];
                float t = fmaf(-2.f, rintf(0.5f * x), x);   // period-2 reduction
                float s1, c1;
                __sincosf(PI_F * t, &s1, &c1);
                xs[j] = x; ss[j] = s1; cs[j] = c1;
            }
        }
        const half2 hm4 = __float2half2_rn(-4.f);
        const half2 h2  = __float2half2_rn(2.f);
        #pragma unroll
        for (int jp = 0; jp < 8; jp++) {
            XH[jp] = __floats2half2_rn(xs[2*jp], xs[2*jp+1]);
            half2 s1 = __floats2half2_rn(ss[2*jp], ss[2*jp+1]);
            half2 c1 = __floats2half2_rn(cs[2*jp], cs[2*jp+1]);
            half2 t2 = __hfma2(__hmul2(s1, s1), hm4, h2);   // 2*cos(2 pi x)
            half2 ns1 = __hneg2(s1), nc1 = __hneg2(c1);
            half2 s3 = __hfma2(t2, s1, s1);
            half2 c3 = __hfma2(t2, c1, nc1);
            half2 s5 = __hfma2(t2, s3, ns1);
            half2 c5 = __hfma2(t2, c3, nc1);
            half2 s7 = __hfma2(t2, s5, __hneg2(s3));
            half2 c7 = __hfma2(t2, c5, __hneg2(c3));
            S9[jp] = __hfma2(t2, s7, __hneg2(s5));
            C9[jp] = __hfma2(t2, c7, __hneg2(c5));
            S1[jp] = s1; C1[jp] = c1; S3[jp] = s3; C3[jp] = c3;
            S5[jp] = s5; C5[jp] = c5;
        }
    }

    for (int h = 0; h < H; h++) {
        __syncthreads();   // previous iteration's smem reads complete
        for (int idx = tid; idx < 64*16; idx += 256) {
            int q = idx >> 4, c = (idx & 15) * 4;
            float4 v = *(const float4*)&g_qp[((size_t)b*S + q0 + q) * D + h*DH + c];
            qs[q*QK_LD+c]   = 0.125f*v.x; qs[q*QK_LD+c+1] = 0.125f*v.y;
            qs[q*QK_LD+c+2] = 0.125f*v.z; qs[q*QK_LD+c+3] = 0.125f*v.w;
        }
        for (int idx = tid; idx < 64*16; idx += 256) {
            int k = idx >> 4, c = (idx & 15) * 4;
            float4 v = *(const float4*)&g_kp[((size_t)b*S + k0 + k) * D + h*DH + c];
            ks[k*QK_LD+c] = v.x; ks[k*QK_LD+c+1] = v.y;
            ks[k*QK_LD+c+2] = v.z; ks[k*QK_LD+c+3] = v.w;
        }
        for (int idx = tid; idx < NB*64; idx += 256) {
            int n = idx >> 6, q = idx & 63;
            cf[idx] = g_coef[(((size_t)n*B + b)*H + h)*S + q0 + q];
        }
        __syncthreads();

        // half2 10-term dot -> ct
        {
            half2 cH0 = __float2half2_rn(cf[0*64 + dq]);
            half2 cH1 = __float2half2_rn(-0.5f * cf[1*64 + dq]);   // fold -0.5 x^2
            half2 cH2 = __float2half2_rn(cf[2*64 + dq]);
            half2 cH3 = __float2half2_rn(cf[3*64 + dq]);
            half2 cH4 = __float2half2_rn(cf[4*64 + dq]);
            half2 cH5 = __float2half2_rn(cf[5*64 + dq]);
            half2 cH6 = __float2half2_rn(cf[6*64 + dq]);
            half2 cH7 = __float2half2_rn(cf[7*64 + dq]);
            half2 cH8 = __float2half2_rn(cf[8*64 + dq]);
            half2 cH9 = __float2half2_rn(cf[9*64 + dq]);
            #pragma unroll
            for (int jp = 0; jp < 8; jp++) {
                half2 a = __hmul2(cH0, XH[jp]);
                a = __hfma2(cH1, __hmul2(XH[jp], XH[jp]), a);
                a = __hfma2(cH2, S1[jp], a);  a = __hfma2(cH3, C1[jp], a);
                a = __hfma2(cH4, S3[jp], a);  a = __hfma2(cH5, C3[jp], a);
                a = __hfma2(cH6, S5[jp], a);  a = __hfma2(cH7, C5[jp], a);
                a = __hfma2(cH8, S9[jp], a);  a = __hfma2(cH9, C9[jp], a);
                float2 f = __half22float2(a);
                *(float2*)&ct[dq*QK_LD + dk + 2*jp] = f;
            }
        }
        __syncthreads();

        // wmma: C(16x32 per warp) = basis_init + (0.125*Q) K^T
        wmma::fragment<wmma::accumulator, 16,16,8, float> c0, c1;
        wmma::load_matrix_sync(c0, ct + wr*16*QK_LD + wc*32,      QK_LD, wmma::mem_row_major);
        wmma::load_matrix_sync(c1, ct + wr*16*QK_LD + wc*32 + 16, QK_LD, wmma::mem_row_major);
        #pragma unroll
        for (int d0 = 0; d0 < DH; d0 += 8) {
            wmma::fragment<wmma::matrix_a, 16,16,8, wmma::precision::tf32, wmma::row_major> af;
            wmma::fragment<wmma::matrix_b, 16,16,8, wmma::precision::tf32, wmma::col_major> b0, b1;
            wmma::load_matrix_sync(af, qs + wr*16*QK_LD + d0, QK_LD);
            wmma::load_matrix_sync(b0, ks + (wc*32)*QK_LD + d0, QK_LD);
            wmma::load_matrix_sync(b1, ks + (wc*32+16)*QK_LD + d0, QK_LD);
            #pragma unroll
            for (int i = 0; i < af.num_elements; i++) af.x[i] = wmma::__float_to_tf32(af.x[i]);
            #pragma unroll
            for (int i = 0; i < b0.num_elements; i++) b0.x[i] = wmma::__float_to_tf32(b0.x[i]);
            #pragma unroll
            for (int i = 0; i < b1.num_elements; i++) b1.x[i] = wmma::__float_to_tf32(b1.x[i]);
            wmma::mma_sync(c0, af, b0, c0);
            wmma::mma_sync(c1, af, b1, c1);
        }
        float* orow = &g_logits[(((size_t)(b*H + h)*S) + q0 + wr*16) * S + k0 + wc*32];
        wmma::store_matrix_sync(orow,      c0, S, wmma::mem_row_major);
        wmma::store_matrix_sync(orow + 16, c1, S, wmma::mem_row_major);
    }
}

// ---------------- fused softmax + PV -----------------------------------------
// Block = (q-tile 64, h, b). Pass A: online row max/sum over S. Pass B: exp-
// normalize tiles, write attn, and wmma-accumulate PV from the smem p-tile.
#define SP_LD 68
__global__ __launch_bounds__(256) void softpv_kernel(float* __restrict__ attn)
{
    __shared__ float pt[64*SP_LD];
    __shared__ float vt[64*SP_LD];
    __shared__ float sm_m[64], sm_iz[64];
    const int b = blockIdx.z, h = blockIdx.y;
    const int q0 = blockIdx.x * 64;
    const int tid = threadIdx.x;
    const int r  = tid >> 2, tq = tid & 3;    // 64 rows x 4 threads
    const int w = tid >> 5;
    const int wr = w >> 1, wc = w & 1;        // 4x2 warps: 16q x 32d each

    const size_t rowbase = ((size_t)(b*H + h)*S + q0) * S;
    const float* lrow = g_logits + rowbase + (size_t)r * S;

    // ---- pass A: online max + sum over this thread's quarter-row ----
    float m = -1e30f, s = 0.f;
    for (int i = 0; i < 32; i++) {
        int c0 = i*64 + tq*16;
        float4 v0 = *(const float4*)&lrow[c0];
        float4 v1 = *(const float4*)&lrow[c0+4];
        float4 v2 = *(const float4*)&lrow[c0+8];
        float4 v3 = *(const float4*)&lrow[c0+12];
        float lm = fmaxf(fmaxf(fmaxf(v0.x,v0.y),fmaxf(v0.z,v0.w)),
                   fmaxf(fmaxf(fmaxf(v1.x,v1.y),fmaxf(v1.z,v1.w)),
                   fmaxf(fmaxf(fmaxf(v2.x,v2.y),fmaxf(v2.z,v2.w)),
                         fmaxf(fmaxf(v3.x,v3.y),fmaxf(v3.z,v3.w)))));
        float mn = fmaxf(m, lm);
        s *= __expf(m - mn);
        s += __expf(v0.x-mn)+__expf(v0.y-mn)+__expf(v0.z-mn)+__expf(v0.w-mn)
           + __expf(v1.x-mn)+__expf(v1.y-mn)+__expf(v1.z-mn)+__expf(v1.w-mn)
           + __expf(v2.x-mn)+__expf(v2.y-mn)+__expf(v2.z-mn)+__expf(v2.w-mn)
           + __expf(v3.x-mn)+__expf(v3.y-mn)+__expf(v3.z-mn)+__expf(v3.w-mn);
        m = mn;
    }
    #pragma unroll
    for (int o = 1; o <= 2; o <<= 1) {
        float mo = __shfl_xor_sync(0xffffffffu, m, o);
        float so = __shfl_xor_sync(0xffffffffu, s, o);
        float mn = fmaxf(m, mo);
        s = s*__expf(m - mn) + so*__expf(mo - mn);
        m = mn;
    }
    if (tq == 0) { sm_m[r] = m; sm_iz[r] = 1.f / s; }
    __syncthreads();

    const float rm = sm_m[r], riz = sm_iz[r];

    wmma::fragment<wmma::accumulator, 16,16,8, float> acc[2];
    wmma::fill_fragment(acc[0], 0.f);
    wmma::fill_fragment(acc[1], 0.f);

    // ---- pass B: tiles of 64 k-cols ----
    float* arow = attn + rowbase + (size_t)r * S;
    for (int k0 = 0; k0 < S; k0 += 64) {
        // V tile (64k x 64d)
        #pragma unroll
        for (int i = 0; i < 4; i++) {
            int idx = i*256 + tid;
            int k = idx >> 4, c = (idx & 15) * 4;
            *(float4*)&vt[k*SP_LD + c] =
                *(const float4*)&g_vp[((size_t)b*S + k0 + k)*D + h*DH + c];
        }
        // p tile: exp-normalize, write attn + smem
        #pragma unroll
        for (int j = 0; j < 4; j++) {
            int c = k0 + tq*16 + j*4;
            float4 v = *(const float4*)&lrow[c];
            v.x = __expf(v.x - rm) * riz;
            v.y = __expf(v.y - rm) * riz;
            v.z = __expf(v.z - rm) * riz;
            v.w = __expf(v.w - rm) * riz;
            *(float4*)&arow[c] = v;
            *(float4*)&pt[r*SP_LD + tq*16 + j*4] = v;
        }
        __syncthreads();
        #pragma unroll
        for (int ch = 0; ch < 8; ch++) {
            wmma::fragment<wmma::matrix_a, 16,16,8, wmma::precision::tf32, wmma::row_major> af;
            wmma::load_matrix_sync(af, pt + wr*16*SP_LD + ch*8, SP_LD);
            #pragma unroll
            for (int i = 0; i < af.num_elements; i++) af.x[i] = wmma::__float_to_tf32(af.x[i]);
            #pragma unroll
            for (int nb = 0; nb < 2; nb++) {
                wmma::fragment<wmma::matrix_b, 16,16,8, wmma::precision::tf32, wmma::row_major> bf;
                wmma::load_matrix_sync(bf, vt + (ch*8)*SP_LD + wc*32 + nb*16, SP_LD);
                #pragma unroll
                for (int i = 0; i < bf.num_elements; i++) bf.x[i] = wmma::__float_to_tf32(bf.x[i]);
                wmma::mma_sync(acc[nb], af, bf, acc[nb]);
            }
        }
        __syncthreads();
    }
    #pragma unroll
    for (int nb = 0; nb < 2; nb++) {
        float* o = &g_attnv[((size_t)b*S + q0 + wr*16)*D + h*DH + wc*32 + nb*16];
        wmma::store_matrix_sync(o, acc[nb], D, wmma::mem_row_major);
    }
}

// -----------------------------------------------------------------------------
extern "C" void kernel_launch(void* const* d_in, const int* in_sizes, int n_in,
                              void* d_out, int out_size)
{
    const float* q     = (const float*)d_in[0];
    const float* k     = (const float*)d_in[1];
    const float* v     = (const float*)d_in[2];
    const float* xdiff = (const float*)d_in[3];
    const float* Wq    = (const float*)d_in[4];
    const float* bq    = (const float*)d_in[5];
    const float* Wk    = (const float*)d_in[6];
    const float* bk    = (const float*)d_in[7];
    const float* Wv    = (const float*)d_in[8];
    const float* bv    = (const float*)d_in[9];
    const float* Wcoef = (const float*)d_in[10];
    const float* bcoef = (const float*)d_in[11];
    const float* Wo    = (const float*)d_in[12];
    const float* bo    = (const float*)d_in[13];
    float* out = (float*)d_out;                       // [B*S*D] out | [B*H*S*S] attn
    float* attn = out + (size_t)B*S*D;

    float *qp, *kp, *vp, *av;
    cudaGetSymbolAddress((void**)&qp, g_qp);
    cudaGetSymbolAddress((void**)&kp, g_kp);
    cudaGetSymbolAddress((void**)&vp, g_vp);
    cudaGetSymbolAddress((void**)&av, g_attnv);

    cudaFuncSetAttribute(logits_kernel, cudaFuncAttributeMaxDynamicSharedMemorySize, LG_SMEM);

    dim3 ggrid(D/128, (B*S)/128);
    gemm_bias_tc<<<ggrid, 256>>>(q, Wq, bq, qp, B*S, D, D);
    gemm_bias_tc<<<ggrid, 256>>>(k, Wk, bk, kp, B*S, D, D);
    gemm_bias_tc<<<ggrid, 256>>>(v, Wv, bv, vp, B*S, D, D);

    coef_kernel<<<(B*S)/16, 256>>>(Wcoef, bcoef);

    logits_kernel<<<dim3(S/64, S/64, B), 256, LG_SMEM>>>(xdiff);

    softpv_kernel<<<dim3(S/64, H, B), 256>>>(attn);

    gemm_bias_tc<<<ggrid, 256>>>(av, Wo, bo, out, B*S, D, D);
}

// round 6
// speedup vs baseline: 1.0338x; 1.0338x over previous
#include <cuda_runtime.h>
#include <cuda_fp16.h>
#include <mma.h>
#include <math.h>

using namespace nvcuda;

#define B 2
#define S 2048
#define D 512
#define H 8
#define DH 64
#define NB 10
#define PI_F 3.14159265358979323846f

// ---------------- scratch ----------------------------------------------------
__device__ float g_qp[B*S*D];
__device__ float g_kp[B*S*D];
__device__ float g_vp[B*S*D];
__device__ float g_coef[NB*B*H*S];                 // [n][b][h][s], pre-scaled by 0.1/8
__device__ float g_logits[(size_t)B*H*S*S];        // 268 MB
__device__ float g_attnv[B*S*D];                   // attn @ V, (b,s, h*64+d)
__device__ float g_wt[D*NB*H];                     // Wcoef transposed: [d][n*8+h]

__device__ __forceinline__ float to_tf32(float x) {
    asm("cvt.rna.tf32.f32 %0, %1;" : "=f"(x) : "f"(x));
    return x;
}

// ---------------- tf32 wmma GEMM:  C = A(MxK) @ W(KxN) + bias ----------------
// tf32 rounding applied ONCE at smem store; fragments consumed raw.
#define GT_ALD 36
#define GT_WLD 132
__global__ __launch_bounds__(256) void gemm_bias_tc(
    const float* __restrict__ A, const float* __restrict__ W,
    const float* __restrict__ bias, float* __restrict__ C,
    int M, int N, int K)
{
    __shared__ float As[128*GT_ALD];   // [m][k]
    __shared__ float Ws[32*GT_WLD];    // [k][n]
    __shared__ float Bt[16*GT_WLD];    // bias tile (rows identical)
    const int bm = blockIdx.y * 128, bn = blockIdx.x * 128;
    const int tid = threadIdx.x, w = tid >> 5;
    const int wm = (w >> 1) * 32, wn = (w & 1) * 64;

    for (int i = tid; i < 16*128; i += 256) {
        int r = i >> 7, c = i & 127;
        Bt[r*GT_WLD + c] = bias[bn + c];
    }
    __syncthreads();

    wmma::fragment<wmma::accumulator, 16,16,8, float> acc[2][4];
    #pragma unroll
    for (int i = 0; i < 2; i++)
        #pragma unroll
        for (int j = 0; j < 4; j++)
            wmma::load_matrix_sync(acc[i][j], Bt + wn + j*16, GT_WLD, wmma::mem_row_major);

    for (int k0 = 0; k0 < K; k0 += 32) {
        #pragma unroll
        for (int i = 0; i < 4; i++) {
            int id = i*256 + tid;
            int row = id >> 3, kc = (id & 7) * 4;
            float4 v = *(const float4*)&A[(size_t)(bm + row) * K + k0 + kc];
            v.x = to_tf32(v.x); v.y = to_tf32(v.y);
            v.z = to_tf32(v.z); v.w = to_tf32(v.w);
            *(float4*)&As[row*GT_ALD + kc] = v;
        }
        #pragma unroll
        for (int i = 0; i < 4; i++) {
            int id = i*256 + tid;
            int kr = id >> 5, nc = (id & 31) * 4;
            float4 v = *(const float4*)&W[(size_t)(k0 + kr) * N + bn + nc];
            v.x = to_tf32(v.x); v.y = to_tf32(v.y);
            v.z = to_tf32(v.z); v.w = to_tf32(v.w);
            *(float4*)&Ws[kr*GT_WLD + nc] = v;
        }
        __syncthreads();
        #pragma unroll
        for (int ks = 0; ks < 4; ks++) {
            wmma::fragment<wmma::matrix_a, 16,16,8, wmma::precision::tf32, wmma::row_major> a0, a1;
            wmma::load_matrix_sync(a0, As + wm*GT_ALD + ks*8, GT_ALD);
            wmma::load_matrix_sync(a1, As + (wm+16)*GT_ALD + ks*8, GT_ALD);
            #pragma unroll
            for (int j = 0; j < 4; j++) {
                wmma::fragment<wmma::matrix_b, 16,16,8, wmma::precision::tf32, wmma::row_major> bf;
                wmma::load_matrix_sync(bf, Ws + (ks*8)*GT_WLD + wn + j*16, GT_WLD);
                wmma::mma_sync(acc[0][j], a0, bf, acc[0][j]);
                wmma::mma_sync(acc[1][j], a1, bf, acc[1][j]);
            }
        }
        __syncthreads();
    }
    #pragma unroll
    for (int i = 0; i < 2; i++)
        #pragma unroll
        for (int j = 0; j < 4; j++)
            wmma::store_matrix_sync(C + (size_t)(bm + wm + i*16) * N + bn + wn + j*16,
                                    acc[i][j], N, wmma::mem_row_major);
}

// ---------------- Wcoef transpose: [n][d][h] -> [d][n*8+h] --------------------
__global__ void transw_kernel(const float* __restrict__ Wcoef)
{
    int i = blockIdx.x * 256 + threadIdx.x;          // 40960 total
    if (i < D*NB*H) {
        int n = i / (D*H), rem = i % (D*H);
        int d = rem / H, h = rem % H;
        g_wt[d*(NB*H) + n*H + h] = Wcoef[i];
    }
}

// ---------------- coef: (B*S x 512) @ (512 x 80) ------------------------------
__global__ void coef_kernel(const float* __restrict__ bcoef)
{
    __shared__ float qsm[16*33];
    __shared__ float wsm[32*80];
    const int bm = blockIdx.x * 16;
    const int t = threadIdx.x;
    const int r = t & 15;             // row within tile
    const int cg = t >> 4;            // col group: 5 cols each (16 groups)
    float acc[5] = {};
    for (int k0 = 0; k0 < D; k0 += 32) {
        #pragma unroll
        for (int i = 0; i < 2; i++) {
            int idx = i*256 + t;
            int rr = idx >> 5, cc = idx & 31;
            qsm[rr*33 + cc] = g_qp[(size_t)(bm + rr) * D + k0 + cc];
        }
        #pragma unroll
        for (int i = 0; i < 3; i++) {
            int idx = i*256 + t;
            if (idx < 640)
                *(float4*)&wsm[idx*4] = *(const float4*)&g_wt[k0*80 + idx*4];
        }
        __syncthreads();
        #pragma unroll 8
        for (int kk = 0; kk < 32; kk++) {
            float a = qsm[r*33 + kk];
            #pragma unroll
            for (int j = 0; j < 5; j++)
                acc[j] += a * wsm[kk*80 + cg*5 + j];
        }
        __syncthreads();
    }
    const int rg = bm + r;
    const int b = rg >> 11, s = rg & (S-1);
    #pragma unroll
    for (int j = 0; j < 5; j++) {
        int nh = cg*5 + j;
        int n = nh >> 3, h = nh & 7;
        float v = acc[j] + bcoef[nh];
        if (n == 1) v = fabsf(v);
        g_coef[(((size_t)n*B + b)*H + h)*S + s] = 0.0125f * v;   // 0.1 / sqrt(64)
    }
}

// ---------------- fused basis + coef-dot + QK^T (wmma tf32, half2 epilogue) --
#define QK_LD  68
#define LG_SMEM ((3*64*QK_LD + NB*64) * 4)
__global__ __launch_bounds__(256, 2) void logits_kernel(const float* __restrict__ xdiff)
{
    extern __shared__ float sm[];
    float* qs  = sm;                          // 64*68 (pre-scaled by 0.125, tf32)
    float* ks  = qs + 64*QK_LD;               // 64*68 (tf32)
    float* ct  = ks + 64*QK_LD;               // 64*68 basis-init / C tile
    float* cf  = ct + 64*QK_LD;               // 10*64

    const int b = blockIdx.z;
    const int q0 = blockIdx.y * 64, k0 = blockIdx.x * 64;
    const int tid = threadIdx.x;
    const int w = tid >> 5;
    const int wr = w >> 1, wc = w & 1;        // 4x2 warp grid over 64x64

    // each thread owns 16 cells: row dq, k strip of 16 (= 8 half2 pairs)
    const int dq = tid >> 2;
    const int dk = (tid & 3) * 16;

    half2 XH[8], S1[8], C1[8], S3[8], C3[8], S5[8], C5[8], S9[8], C9[8];
    {
        float xs[16], ss[16], cs[16];
        const float* xp = &xdiff[((size_t)b*S + q0 + dq) * S + k0 + dk];
        #pragma unroll
        for (int j4 = 0; j4 < 4; j4++) {
            float4 x4 = *(const float4*)&xp[j4*4];
            float xv[4] = {x4.x, x4.y, x4.z, x4.w};
            #pragma unroll
            for (int u = 0; u < 4; u++) {
                int j = j4*4 + u;
                float x = xv[u];
                float t = fmaf(-2.f, rintf(0.5f * x), x);   // period-2 reduction
                float s1, c1;
                __sincosf(PI_F * t, &s1, &c1);
                xs[j] = x; ss[j] = s1; cs[j] = c1;
            }
        }
        const half2 hm4 = __float2half2_rn(-4.f);
        const half2 h2  = __float2half2_rn(2.f);
        #pragma unroll
        for (int jp = 0; jp < 8; jp++) {
            XH[jp] = __floats2half2_rn(xs[2*jp], xs[2*jp+1]);
            half2 s1 = __floats2half2_rn(ss[2*jp], ss[2*jp+1]);
            half2 c1 = __floats2half2_rn(cs[2*jp], cs[2*jp+1]);
            half2 t2 = __hfma2(__hmul2(s1, s1), hm4, h2);   // 2*cos(2 pi x)
            half2 ns1 = __hneg2(s1), nc1 = __hneg2(c1);
            half2 s3 = __hfma2(t2, s1, s1);
            half2 c3 = __hfma2(t2, c1, nc1);
            half2 s5 = __hfma2(t2, s3, ns1);
            half2 c5 = __hfma2(t2, c3, nc1);
            half2 s7 = __hfma2(t2, s5, __hneg2(s3));
            half2 c7 = __hfma2(t2, c5, __hneg2(c3));
            S9[jp] = __hfma2(t2, s7, __hneg2(s5));
            C9[jp] = __hfma2(t2, c7, __hneg2(c5));
            S1[jp] = s1; C1[jp] = c1; S3[jp] = s3; C3[jp] = c3;
            S5[jp] = s5; C5[jp] = c5;
        }
    }

    for (int h = 0; h < H; h++) {
        __syncthreads();   // previous iteration's smem reads complete
        for (int idx = tid; idx < 64*16; idx += 256) {
            int q = idx >> 4, c = (idx & 15) * 4;
            float4 v = *(const float4*)&g_qp[((size_t)b*S + q0 + q) * D + h*DH + c];
            qs[q*QK_LD+c]   = to_tf32(0.125f*v.x);
            qs[q*QK_LD+c+1] = to_tf32(0.125f*v.y);
            qs[q*QK_LD+c+2] = to_tf32(0.125f*v.z);
            qs[q*QK_LD+c+3] = to_tf32(0.125f*v.w);
        }
        for (int idx = tid; idx < 64*16; idx += 256) {
            int k = idx >> 4, c = (idx & 15) * 4;
            float4 v = *(const float4*)&g_kp[((size_t)b*S + k0 + k) * D + h*DH + c];
            ks[k*QK_LD+c]   = to_tf32(v.x);
            ks[k*QK_LD+c+1] = to_tf32(v.y);
            ks[k*QK_LD+c+2] = to_tf32(v.z);
            ks[k*QK_LD+c+3] = to_tf32(v.w);
        }
        for (int idx = tid; idx < NB*64; idx += 256) {
            int n = idx >> 6, q = idx & 63;
            cf[idx] = g_coef[(((size_t)n*B + b)*H + h)*S + q0 + q];
        }
        __syncthreads();

        // half2 10-term dot -> ct
        {
            half2 cH0 = __float2half2_rn(cf[0*64 + dq]);
            half2 cH1 = __float2half2_rn(-0.5f * cf[1*64 + dq]);   // fold -0.5 x^2
            half2 cH2 = __float2half2_rn(cf[2*64 + dq]);
            half2 cH3 = __float2half2_rn(cf[3*64 + dq]);
            half2 cH4 = __float2half2_rn(cf[4*64 + dq]);
            half2 cH5 = __float2half2_rn(cf[5*64 + dq]);
            half2 cH6 = __float2half2_rn(cf[6*64 + dq]);
            half2 cH7 = __float2half2_rn(cf[7*64 + dq]);
            half2 cH8 = __float2half2_rn(cf[8*64 + dq]);
            half2 cH9 = __float2half2_rn(cf[9*64 + dq]);
            #pragma unroll
            for (int jp = 0; jp < 8; jp++) {
                half2 a = __hmul2(cH0, XH[jp]);
                a = __hfma2(cH1, __hmul2(XH[jp], XH[jp]), a);
                a = __hfma2(cH2, S1[jp], a);  a = __hfma2(cH3, C1[jp], a);
                a = __hfma2(cH4, S3[jp], a);  a = __hfma2(cH5, C3[jp], a);
                a = __hfma2(cH6, S5[jp], a);  a = __hfma2(cH7, C5[jp], a);
                a = __hfma2(cH8, S9[jp], a);  a = __hfma2(cH9, C9[jp], a);
                float2 f = __half22float2(a);
                *(float2*)&ct[dq*QK_LD + dk + 2*jp] = f;
            }
        }
        __syncthreads();

        // wmma: C(16x32 per warp) = basis_init + (0.125*Q) K^T
        wmma::fragment<wmma::accumulator, 16,16,8, float> c0, c1;
        wmma::load_matrix_sync(c0, ct + wr*16*QK_LD + wc*32,      QK_LD, wmma::mem_row_major);
        wmma::load_matrix_sync(c1, ct + wr*16*QK_LD + wc*32 + 16, QK_LD, wmma::mem_row_major);
        #pragma unroll
        for (int d0 = 0; d0 < DH; d0 += 8) {
            wmma::fragment<wmma::matrix_a, 16,16,8, wmma::precision::tf32, wmma::row_major> af;
            wmma::fragment<wmma::matrix_b, 16,16,8, wmma::precision::tf32, wmma::col_major> b0, b1;
            wmma::load_matrix_sync(af, qs + wr*16*QK_LD + d0, QK_LD);
            wmma::load_matrix_sync(b0, ks + (wc*32)*QK_LD + d0, QK_LD);
            wmma::load_matrix_sync(b1, ks + (wc*32+16)*QK_LD + d0, QK_LD);
            wmma::mma_sync(c0, af, b0, c0);
            wmma::mma_sync(c1, af, b1, c1);
        }
        float* orow = &g_logits[(((size_t)(b*H + h)*S) + q0 + wr*16) * S + k0 + wc*32];
        wmma::store_matrix_sync(orow,      c0, S, wmma::mem_row_major);
        wmma::store_matrix_sync(orow + 16, c1, S, wmma::mem_row_major);
    }
}

// ---------------- fused softmax + PV -----------------------------------------
#define SP_LD 68
__global__ __launch_bounds__(256) void softpv_kernel(float* __restrict__ attn)
{
    __shared__ float pt[64*SP_LD];
    __shared__ float vt[64*SP_LD];
    __shared__ float sm_m[64], sm_iz[64];
    const int b = blockIdx.z, h = blockIdx.y;
    const int q0 = blockIdx.x * 64;
    const int tid = threadIdx.x;
    const int r  = tid >> 2, tq = tid & 3;    // 64 rows x 4 threads
    const int w = tid >> 5;
    const int wr = w >> 1, wc = w & 1;        // 4x2 warps: 16q x 32d each

    const size_t rowbase = ((size_t)(b*H + h)*S + q0) * S;
    const float* lrow = g_logits + rowbase + (size_t)r * S;

    // ---- pass A: online max + sum over this thread's quarter-row ----
    float m = -1e30f, s = 0.f;
    for (int i = 0; i < 32; i++) {
        int c0 = i*64 + tq*16;
        float4 v0 = *(const float4*)&lrow[c0];
        float4 v1 = *(const float4*)&lrow[c0+4];
        float4 v2 = *(const float4*)&lrow[c0+8];
        float4 v3 = *(const float4*)&lrow[c0+12];
        float lm = fmaxf(fmaxf(fmaxf(v0.x,v0.y),fmaxf(v0.z,v0.w)),
                   fmaxf(fmaxf(fmaxf(v1.x,v1.y),fmaxf(v1.z,v1.w)),
                   fmaxf(fmaxf(fmaxf(v2.x,v2.y),fmaxf(v2.z,v2.w)),
                         fmaxf(fmaxf(v3.x,v3.y),fmaxf(v3.z,v3.w)))));
        float mn = fmaxf(m, lm);
        s *= __expf(m - mn);
        s += __expf(v0.x-mn)+__expf(v0.y-mn)+__expf(v0.z-mn)+__expf(v0.w-mn)
           + __expf(v1.x-mn)+__expf(v1.y-mn)+__expf(v1.z-mn)+__expf(v1.w-mn)
           + __expf(v2.x-mn)+__expf(v2.y-mn)+__expf(v2.z-mn)+__expf(v2.w-mn)
           + __expf(v3.x-mn)+__expf(v3.y-mn)+__expf(v3.z-mn)+__expf(v3.w-mn);
        m = mn;
    }
    #pragma unroll
    for (int o = 1; o <= 2; o <<= 1) {
        float mo = __shfl_xor_sync(0xffffffffu, m, o);
        float so = __shfl_xor_sync(0xffffffffu, s, o);
        float mn = fmaxf(m, mo);
        s = s*__expf(m - mn) + so*__expf(mo - mn);
        m = mn;
    }
    if (tq == 0) { sm_m[r] = m; sm_iz[r] = 1.f / s; }
    __syncthreads();

    const float rm = sm_m[r], riz = sm_iz[r];

    wmma::fragment<wmma::accumulator, 16,16,8, float> acc[2];
    wmma::fill_fragment(acc[0], 0.f);
    wmma::fill_fragment(acc[1], 0.f);

    // ---- pass B: tiles of 64 k-cols ----
    float* arow = attn + rowbase + (size_t)r * S;
    for (int k0 = 0; k0 < S; k0 += 64) {
        // V tile (64k x 64d), tf32-rounded at store
        #pragma unroll
        for (int i = 0; i < 4; i++) {
            int idx = i*256 + tid;
            int k = idx >> 4, c = (idx & 15) * 4;
            float4 v = *(const float4*)&g_vp[((size_t)b*S + k0 + k)*D + h*DH + c];
            v.x = to_tf32(v.x); v.y = to_tf32(v.y);
            v.z = to_tf32(v.z); v.w = to_tf32(v.w);
            *(float4*)&vt[k*SP_LD + c] = v;
        }
        // p tile: exp-normalize, write attn (fp32) + smem (tf32)
        #pragma unroll
        for (int j = 0; j < 4; j++) {
            int c = k0 + tq*16 + j*4;
            float4 v = *(const float4*)&lrow[c];
            v.x = __expf(v.x - rm) * riz;
            v.y = __expf(v.y - rm) * riz;
            v.z = __expf(v.z - rm) * riz;
            v.w = __expf(v.w - rm) * riz;
            *(float4*)&arow[c] = v;
            v.x = to_tf32(v.x); v.y = to_tf32(v.y);
            v.z = to_tf32(v.z); v.w = to_tf32(v.w);
            *(float4*)&pt[r*SP_LD + tq*16 + j*4] = v;
        }
        __syncthreads();
        #pragma unroll
        for (int ch = 0; ch < 8; ch++) {
            wmma::fragment<wmma::matrix_a, 16,16,8, wmma::precision::tf32, wmma::row_major> af;
            wmma::load_matrix_sync(af, pt + wr*16*SP_LD + ch*8, SP_LD);
            #pragma unroll
            for (int nb = 0; nb < 2; nb++) {
                wmma::fragment<wmma::matrix_b, 16,16,8, wmma::precision::tf32, wmma::row_major> bf;
                wmma::load_matrix_sync(bf, vt + (ch*8)*SP_LD + wc*32 + nb*16, SP_LD);
                wmma::mma_sync(acc[nb], af, bf, acc[nb]);
            }
        }
        __syncthreads();
    }
    #pragma unroll
    for (int nb = 0; nb < 2; nb++) {
        float* o = &g_attnv[((size_t)b*S + q0 + wr*16)*D + h*DH + wc*32 + nb*16];
        wmma::store_matrix_sync(o, acc[nb], D, wmma::mem_row_major);
    }
}

// -----------------------------------------------------------------------------
extern "C" void kernel_launch(void* const* d_in, const int* in_sizes, int n_in,
                              void* d_out, int out_size)
{
    const float* q     = (const float*)d_in[0];
    const float* k     = (const float*)d_in[1];
    const float* v     = (const float*)d_in[2];
    const float* xdiff = (const float*)d_in[3];
    const float* Wq    = (const float*)d_in[4];
    const float* bq    = (const float*)d_in[5];
    const float* Wk    = (const float*)d_in[6];
    const float* bk    = (const float*)d_in[7];
    const float* Wv    = (const float*)d_in[8];
    const float* bv    = (const float*)d_in[9];
    const float* Wcoef = (const float*)d_in[10];
    const float* bcoef = (const float*)d_in[11];
    const float* Wo    = (const float*)d_in[12];
    const float* bo    = (const float*)d_in[13];
    float* out = (float*)d_out;                       // [B*S*D] out | [B*H*S*S] attn
    float* attn = out + (size_t)B*S*D;

    float *qp, *kp, *vp, *av;
    cudaGetSymbolAddress((void**)&qp, g_qp);
    cudaGetSymbolAddress((void**)&kp, g_kp);
    cudaGetSymbolAddress((void**)&vp, g_vp);
    cudaGetSymbolAddress((void**)&av, g_attnv);

    cudaFuncSetAttribute(logits_kernel, cudaFuncAttributeMaxDynamicSharedMemorySize, LG_SMEM);

    dim3 ggrid(D/128, (B*S)/128);
    gemm_bias_tc<<<ggrid, 256>>>(q, Wq, bq, qp, B*S, D, D);
    gemm_bias_tc<<<ggrid, 256>>>(k, Wk, bk, kp, B*S, D, D);
    gemm_bias_tc<<<ggrid, 256>>>(v, Wv, bv, vp, B*S, D, D);

    transw_kernel<<<(D*NB*H + 255)/256, 256>>>(Wcoef);
    coef_kernel<<<(B*S)/16, 256>>>(bcoef);

    logits_kernel<<<dim3(S/64, S/64, B), 256, LG_SMEM>>>(xdiff);

    softpv_kernel<<<dim3(S/64, H, B), 256>>>(attn);

    gemm_bias_tc<<<ggrid, 256>>>(av, Wo, bo, out, B*S, D, D);
}

// round 7
// speedup vs baseline: 1.1324x; 1.0954x over previous
#include <cuda_runtime.h>
#include <mma.h>
#include <math.h>

using namespace nvcuda;

#define B 2
#define S 2048
#define D 512
#define H 8
#define DH 64
#define NB 10
#define PI_F 3.14159265358979323846f

// ---------------- scratch ----------------------------------------------------
__device__ float g_qp[B*S*D];
__device__ float g_kp[B*S*D];
__device__ float g_vp[B*S*D];
__device__ float g_coef[NB*B*H*S];                 // [n][b][h][s], pre-scaled by 0.1/8
__device__ float g_logits[(size_t)B*H*S*S];        // holds exp(logit)
__device__ float g_rowsum[B*H*S];                  // sum of exp per row
__device__ float g_attnv[B*S*D];                   // attn @ V, (b,s, h*64+d)
__device__ float g_wt[D*NB*H];                     // Wcoef transposed: [d][n*8+h]

__device__ __forceinline__ float to_tf32(float x) {
    asm("cvt.rna.tf32.f32 %0, %1;" : "=f"(x) : "f"(x));
    return x;
}

// ---------------- tf32 wmma GEMM:  C = A(MxK) @ W(KxN) + bias ----------------
#define GT_ALD 36
#define GT_WLD 132
__global__ __launch_bounds__(256) void gemm_bias_tc(
    const float* __restrict__ A, const float* __restrict__ W,
    const float* __restrict__ bias, float* __restrict__ C,
    int M, int N, int K)
{
    __shared__ float As[128*GT_ALD];   // [m][k]
    __shared__ float Ws[32*GT_WLD];    // [k][n]
    __shared__ float Bt[16*GT_WLD];    // bias tile (rows identical)
    const int bm = blockIdx.y * 128, bn = blockIdx.x * 128;
    const int tid = threadIdx.x, w = tid >> 5;
    const int wm = (w >> 1) * 32, wn = (w & 1) * 64;

    for (int i = tid; i < 16*128; i += 256) {
        int r = i >> 7, c = i & 127;
        Bt[r*GT_WLD + c] = bias[bn + c];
    }
    __syncthreads();

    wmma::fragment<wmma::accumulator, 16,16,8, float> acc[2][4];
    #pragma unroll
    for (int i = 0; i < 2; i++)
        #pragma unroll
        for (int j = 0; j < 4; j++)
            wmma::load_matrix_sync(acc[i][j], Bt + wn + j*16, GT_WLD, wmma::mem_row_major);

    for (int k0 = 0; k0 < K; k0 += 32) {
        #pragma unroll
        for (int i = 0; i < 4; i++) {
            int id = i*256 + tid;
            int row = id >> 3, kc = (id & 7) * 4;
            float4 v = *(const float4*)&A[(size_t)(bm + row) * K + k0 + kc];
            v.x = to_tf32(v.x); v.y = to_tf32(v.y);
            v.z = to_tf32(v.z); v.w = to_tf32(v.w);
            *(float4*)&As[row*GT_ALD + kc] = v;
        }
        #pragma unroll
        for (int i = 0; i < 4; i++) {
            int id = i*256 + tid;
            int kr = id >> 5, nc = (id & 31) * 4;
            float4 v = *(const float4*)&W[(size_t)(k0 + kr) * N + bn + nc];
            v.x = to_tf32(v.x); v.y = to_tf32(v.y);
            v.z = to_tf32(v.z); v.w = to_tf32(v.w);
            *(float4*)&Ws[kr*GT_WLD + nc] = v;
        }
        __syncthreads();
        #pragma unroll
        for (int ks = 0; ks < 4; ks++) {
            wmma::fragment<wmma::matrix_a, 16,16,8, wmma::precision::tf32, wmma::row_major> a0, a1;
            wmma::load_matrix_sync(a0, As + wm*GT_ALD + ks*8, GT_ALD);
            wmma::load_matrix_sync(a1, As + (wm+16)*GT_ALD + ks*8, GT_ALD);
            #pragma unroll
            for (int j = 0; j < 4; j++) {
                wmma::fragment<wmma::matrix_b, 16,16,8, wmma::precision::tf32, wmma::row_major> bf;
                wmma::load_matrix_sync(bf, Ws + (ks*8)*GT_WLD + wn + j*16, GT_WLD);
                wmma::mma_sync(acc[0][j], a0, bf, acc[0][j]);
                wmma::mma_sync(acc[1][j], a1, bf, acc[1][j]);
            }
        }
        __syncthreads();
    }
    #pragma unroll
    for (int i = 0; i < 2; i++)
        #pragma unroll
        for (int j = 0; j < 4; j++)
            wmma::store_matrix_sync(C + (size_t)(bm + wm + i*16) * N + bn + wn + j*16,
                                    acc[i][j], N, wmma::mem_row_major);
}

// ---------------- Wcoef transpose: [n][d][h] -> [d][n*8+h] --------------------
__global__ void transw_kernel(const float* __restrict__ Wcoef)
{
    int i = blockIdx.x * 256 + threadIdx.x;          // 40960 total
    if (i < D*NB*H) {
        int n = i / (D*H), rem = i % (D*H);
        int d = rem / H, h = rem % H;
        g_wt[d*(NB*H) + n*H + h] = Wcoef[i];
    }
}

// ---------------- coef: (B*S x 512) @ (512 x 80) ------------------------------
__global__ void coef_kernel(const float* __restrict__ bcoef)
{
    __shared__ float qsm[16*33];
    __shared__ float wsm[32*80];
    const int bm = blockIdx.x * 16;
    const int t = threadIdx.x;
    const int r = t & 15;             // row within tile
    const int cg = t >> 4;            // col group: 5 cols each (16 groups)
    float acc[5] = {};
    for (int k0 = 0; k0 < D; k0 += 32) {
        #pragma unroll
        for (int i = 0; i < 2; i++) {
            int idx = i*256 + t;
            int rr = idx >> 5, cc = idx & 31;
            qsm[rr*33 + cc] = g_qp[(size_t)(bm + rr) * D + k0 + cc];
        }
        #pragma unroll
        for (int i = 0; i < 3; i++) {
            int idx = i*256 + t;
            if (idx < 640)
                *(float4*)&wsm[idx*4] = *(const float4*)&g_wt[k0*80 + idx*4];
        }
        __syncthreads();
        #pragma unroll 8
        for (int kk = 0; kk < 32; kk++) {
            float a = qsm[r*33 + kk];
            #pragma unroll
            for (int j = 0; j < 5; j++)
                acc[j] += a * wsm[kk*80 + cg*5 + j];
        }
        __syncthreads();
    }
    const int rg = bm + r;
    const int b = rg >> 11, s = rg & (S-1);
    #pragma unroll
    for (int j = 0; j < 5; j++) {
        int nh = cg*5 + j;
        int n = nh >> 3, h = nh & 7;
        float v = acc[j] + bcoef[nh];
        if (n == 1) v = fabsf(v);
        g_coef[(((size_t)n*B + b)*H + h)*S + s] = 0.0125f * v;   // 0.1 / sqrt(64)
    }
}

// ---------------- fused basis + coef-dot + QK^T + exp + rowsum ---------------
// One head per block. grid: (B*H, S/64, S/64) — bh innermost keeps xdiff L2-hot.
// Writes exp(logit) to g_logits and atomically accumulates row sums.
#define QK_LD  68
#define LG_SMEM ((3*64*QK_LD + NB*64) * 4)
__global__ __launch_bounds__(256) void logits_kernel(const float* __restrict__ xdiff)
{
    extern __shared__ float sm[];
    float* qs  = sm;                          // 64*68 (pre-scaled by 0.125, tf32)
    float* ks  = qs + 64*QK_LD;               // 64*68 (tf32)
    float* ct  = ks + 64*QK_LD;               // 64*68 basis-init / C tile
    float* cf  = ct + 64*QK_LD;               // 10*64

    const int bh = blockIdx.x, b = bh >> 3, h = bh & 7;
    const int k0 = blockIdx.y * 64, q0 = blockIdx.z * 64;
    const int tid = threadIdx.x;
    const int w = tid >> 5;
    const int wr = w >> 1, wc = w & 1;        // 4x2 warp grid over 64x64

    // each thread owns 16 cells: row dq, k strip of 16
    const int dq = tid >> 2;
    const int dk = (tid & 3) * 16;

    // tile loads
    for (int idx = tid; idx < 64*16; idx += 256) {
        int q = idx >> 4, c = (idx & 15) * 4;
        float4 v = *(const float4*)&g_qp[((size_t)b*S + q0 + q) * D + h*DH + c];
        qs[q*QK_LD+c]   = to_tf32(0.125f*v.x);
        qs[q*QK_LD+c+1] = to_tf32(0.125f*v.y);
        qs[q*QK_LD+c+2] = to_tf32(0.125f*v.z);
        qs[q*QK_LD+c+3] = to_tf32(0.125f*v.w);
    }
    for (int idx = tid; idx < 64*16; idx += 256) {
        int k = idx >> 4, c = (idx & 15) * 4;
        float4 v = *(const float4*)&g_kp[((size_t)b*S + k0 + k) * D + h*DH + c];
        ks[k*QK_LD+c]   = to_tf32(v.x);
        ks[k*QK_LD+c+1] = to_tf32(v.y);
        ks[k*QK_LD+c+2] = to_tf32(v.z);
        ks[k*QK_LD+c+3] = to_tf32(v.w);
    }
    if (tid < NB*64) {
        int n = tid >> 6, q = tid & 63;
        cf[tid] = g_coef[(((size_t)n*B + b)*H + h)*S + q0 + q];
    }
    if (tid + 256 < NB*64) {
        int idx = tid + 256;
        int n = idx >> 6, q = idx & 63;
        cf[idx] = g_coef[(((size_t)n*B + b)*H + h)*S + q0 + q];
    }
    if (tid + 512 < NB*64) {
        int idx = tid + 512;
        int n = idx >> 6, q = idx & 63;
        cf[idx] = g_coef[(((size_t)n*B + b)*H + h)*S + q0 + q];
    }

    // basis ladder + 10-term dot (fp32) -> ct, concurrent with tile loads
    {
        float c0 = __ldg(&g_coef[(((size_t)0*B + b)*H + h)*S + q0 + dq]);
        // (use smem cf after sync instead — need it anyway; do after sync)
        (void)c0;
    }
    __syncthreads();

    {
        float c0 = cf[0*64 + dq], c1f = -0.5f * cf[1*64 + dq];
        float c2 = cf[2*64 + dq], c3 = cf[3*64 + dq];
        float c4 = cf[4*64 + dq], c5 = cf[5*64 + dq];
        float c6 = cf[6*64 + dq], c7 = cf[7*64 + dq];
        float c8 = cf[8*64 + dq], c9 = cf[9*64 + dq];
        const float* xp = &xdiff[((size_t)b*S + q0 + dq) * S + k0 + dk];
        #pragma unroll
        for (int j4 = 0; j4 < 4; j4++) {
            float4 x4 = *(const float4*)&xp[j4*4];
            float xv[4] = {x4.x, x4.y, x4.z, x4.w};
            float o[4];
            #pragma unroll
            for (int u = 0; u < 4; u++) {
                float x = xv[u];
                float t = fmaf(-2.f, rintf(0.5f * x), x);   // period-2 reduction
                float s1, cc1;
                __sincosf(PI_F * t, &s1, &cc1);
                float tc2 = 2.f * fmaf(-2.f*s1, s1, 1.f);   // 2*cos(2 pi x)
                float s3 = fmaf(tc2, s1,  s1),  cc3 = fmaf(tc2, cc1, -cc1);
                float s5 = fmaf(tc2, s3, -s1),  cc5 = fmaf(tc2, cc3, -cc1);
                float s7 = fmaf(tc2, s5, -s3),  cc7 = fmaf(tc2, cc5, -cc3);
                float s9 = fmaf(tc2, s7, -s5),  cc9 = fmaf(tc2, cc7, -cc5);
                float a = c0 * x;
                a = fmaf(c1f, x*x, a);
                a = fmaf(c2, s1, a);  a = fmaf(c3, cc1, a);
                a = fmaf(c4, s3, a);  a = fmaf(c5, cc3, a);
                a = fmaf(c6, s5, a);  a = fmaf(c7, cc5, a);
                a = fmaf(c8, s9, a);  a = fmaf(c9, cc9, a);
                o[u] = a;
            }
            *(float4*)&ct[dq*QK_LD + dk + j4*4] = make_float4(o[0], o[1], o[2], o[3]);
        }
    }
    __syncthreads();

    // wmma: C(16x32 per warp) = basis_init + (0.125*Q) K^T  -> back to smem ct
    {
        wmma::fragment<wmma::accumulator, 16,16,8, float> c0, c1;
        wmma::load_matrix_sync(c0, ct + wr*16*QK_LD + wc*32,      QK_LD, wmma::mem_row_major);
        wmma::load_matrix_sync(c1, ct + wr*16*QK_LD + wc*32 + 16, QK_LD, wmma::mem_row_major);
        #pragma unroll
        for (int d0 = 0; d0 < DH; d0 += 8) {
            wmma::fragment<wmma::matrix_a, 16,16,8, wmma::precision::tf32, wmma::row_major> af;
            wmma::fragment<wmma::matrix_b, 16,16,8, wmma::precision::tf32, wmma::col_major> b0, b1;
            wmma::load_matrix_sync(af, qs + wr*16*QK_LD + d0, QK_LD);
            wmma::load_matrix_sync(b0, ks + (wc*32)*QK_LD + d0, QK_LD);
            wmma::load_matrix_sync(b1, ks + (wc*32+16)*QK_LD + d0, QK_LD);
            wmma::mma_sync(c0, af, b0, c0);
            wmma::mma_sync(c1, af, b1, c1);
        }
        __syncthreads();   // done reading ct as init
        wmma::store_matrix_sync(ct + wr*16*QK_LD + wc*32,      c0, QK_LD, wmma::mem_row_major);
        wmma::store_matrix_sync(ct + wr*16*QK_LD + wc*32 + 16, c1, QK_LD, wmma::mem_row_major);
    }
    __syncthreads();

    // exp, partial row-sum (atomic), write e to g_logits
    {
        float ssum = 0.f;
        float* orow = &g_logits[((size_t)bh*S + q0 + dq) * S + k0 + dk];
        #pragma unroll
        for (int j4 = 0; j4 < 4; j4++) {
            float4 v = *(const float4*)&ct[dq*QK_LD + dk + j4*4];
            v.x = __expf(v.x); v.y = __expf(v.y);
            v.z = __expf(v.z); v.w = __expf(v.w);
            ssum += v.x + v.y + v.z + v.w;
            *(float4*)&orow[j4*4] = v;
        }
        ssum += __shfl_xor_sync(0xffffffffu, ssum, 1);
        ssum += __shfl_xor_sync(0xffffffffu, ssum, 2);
        if ((tid & 3) == 0)
            atomicAdd(&g_rowsum[(size_t)bh*S + q0 + dq], ssum);
    }
}

// ---------------- fused normalize + PV (single pass) -------------------------
#define SP_LD 68
__global__ __launch_bounds__(256) void softpv_kernel(float* __restrict__ attn)
{
    __shared__ float pt[64*SP_LD];
    __shared__ float vt[64*SP_LD];
    const int b = blockIdx.z, h = blockIdx.y;
    const int q0 = blockIdx.x * 64;
    const int tid = threadIdx.x;
    const int r  = tid >> 2, tq = tid & 3;    // 64 rows x 4 threads
    const int w = tid >> 5;
    const int wr = w >> 1, wc = w & 1;        // 4x2 warps: 16q x 32d each

    const size_t rowbase = ((size_t)(b*H + h)*S + q0) * S;
    const float* lrow = g_logits + rowbase + (size_t)r * S;
    const float riz = 1.f / g_rowsum[(size_t)(b*H + h)*S + q0 + r];

    wmma::fragment<wmma::accumulator, 16,16,8, float> acc[2];
    wmma::fill_fragment(acc[0], 0.f);
    wmma::fill_fragment(acc[1], 0.f);

    float* arow = attn + rowbase + (size_t)r * S;
    for (int k0 = 0; k0 < S; k0 += 64) {
        // V tile (64k x 64d), tf32-rounded at store
        #pragma unroll
        for (int i = 0; i < 4; i++) {
            int idx = i*256 + tid;
            int k = idx >> 4, c = (idx & 15) * 4;
            float4 v = *(const float4*)&g_vp[((size_t)b*S + k0 + k)*D + h*DH + c];
            v.x = to_tf32(v.x); v.y = to_tf32(v.y);
            v.z = to_tf32(v.z); v.w = to_tf32(v.w);
            *(float4*)&vt[k*SP_LD + c] = v;
        }
        // p tile: e * riz, write attn (fp32) + smem (tf32)
        #pragma unroll
        for (int j = 0; j < 4; j++) {
            int c = k0 + tq*16 + j*4;
            float4 v = *(const float4*)&lrow[c];
            v.x *= riz; v.y *= riz; v.z *= riz; v.w *= riz;
            *(float4*)&arow[c] = v;
            v.x = to_tf32(v.x); v.y = to_tf32(v.y);
            v.z = to_tf32(v.z); v.w = to_tf32(v.w);
            *(float4*)&pt[r*SP_LD + tq*16 + j*4] = v;
        }
        __syncthreads();
        #pragma unroll
        for (int ch = 0; ch < 8; ch++) {
            wmma::fragment<wmma::matrix_a, 16,16,8, wmma::precision::tf32, wmma::row_major> af;
            wmma::load_matrix_sync(af, pt + wr*16*SP_LD + ch*8, SP_LD);
            #pragma unroll
            for (int nb = 0; nb < 2; nb++) {
                wmma::fragment<wmma::matrix_b, 16,16,8, wmma::precision::tf32, wmma::row_major> bf;
                wmma::load_matrix_sync(bf, vt + (ch*8)*SP_LD + wc*32 + nb*16, SP_LD);
                wmma::mma_sync(acc[nb], af, bf, acc[nb]);
            }
        }
        __syncthreads();
    }
    #pragma unroll
    for (int nb = 0; nb < 2; nb++) {
        float* o = &g_attnv[((size_t)b*S + q0 + wr*16)*D + h*DH + wc*32 + nb*16];
        wmma::store_matrix_sync(o, acc[nb], D, wmma::mem_row_major);
    }
}

// -----------------------------------------------------------------------------
extern "C" void kernel_launch(void* const* d_in, const int* in_sizes, int n_in,
                              void* d_out, int out_size)
{
    const float* q     = (const float*)d_in[0];
    const float* k     = (const float*)d_in[1];
    const float* v     = (const float*)d_in[2];
    const float* xdiff = (const float*)d_in[3];
    const float* Wq    = (const float*)d_in[4];
    const float* bq    = (const float*)d_in[5];
    const float* Wk    = (const float*)d_in[6];
    const float* bk    = (const float*)d_in[7];
    const float* Wv    = (const float*)d_in[8];
    const float* bv    = (const float*)d_in[9];
    const float* Wcoef = (const float*)d_in[10];
    const float* bcoef = (const float*)d_in[11];
    const float* Wo    = (const float*)d_in[12];
    const float* bo    = (const float*)d_in[13];
    float* out = (float*)d_out;                       // [B*S*D] out | [B*H*S*S] attn
    float* attn = out + (size_t)B*S*D;

    float *qp, *kp, *vp, *av, *rs;
    cudaGetSymbolAddress((void**)&qp, g_qp);
    cudaGetSymbolAddress((void**)&kp, g_kp);
    cudaGetSymbolAddress((void**)&vp, g_vp);
    cudaGetSymbolAddress((void**)&av, g_attnv);
    cudaGetSymbolAddress((void**)&rs, g_rowsum);

    cudaFuncSetAttribute(logits_kernel, cudaFuncAttributeMaxDynamicSharedMemorySize, LG_SMEM);

    cudaMemsetAsync(rs, 0, (size_t)B*H*S*sizeof(float), 0);

    dim3 ggrid(D/128, (B*S)/128);
    gemm_bias_tc<<<ggrid, 256>>>(q, Wq, bq, qp, B*S, D, D);
    gemm_bias_tc<<<ggrid, 256>>>(k, Wk, bk, kp, B*S, D, D);
    gemm_bias_tc<<<ggrid, 256>>>(v, Wv, bv, vp, B*S, D, D);

    transw_kernel<<<(D*NB*H + 255)/256, 256>>>(Wcoef);
    coef_kernel<<<(B*S)/16, 256>>>(bcoef);

    logits_kernel<<<dim3(B*H, S/64, S/64), 256, LG_SMEM>>>(xdiff);

    softpv_kernel<<<dim3(S/64, H, B), 256>>>(attn);

    gemm_bias_tc<<<ggrid, 256>>>(av, Wo, bo, out, B*S, D, D);
}

// round 8
// speedup vs baseline: 1.3795x; 1.2181x over previous
#include <cuda_runtime.h>
#include <cuda_fp16.h>
#include <mma.h>
#include <math.h>

using namespace nvcuda;

#define B 2
#define S 2048
#define D 512
#define H 8
#define DH 64
#define NB 10
#define PI_F 3.14159265358979323846f

// ---------------- scratch ----------------------------------------------------
__device__ float g_qp[B*S*D];
__device__ float g_kp[B*S*D];
__device__ float g_vp[B*S*D];
__device__ __half g_vph[B*S*D];                    // half copy of vp
__device__ float g_coef[NB*B*H*S];                 // [n][b][h][s], pre-scaled by 0.1/8
__device__ __half g_e[(size_t)B*H*S*S];            // exp(logit) in fp16 (134 MB)
__device__ float g_rowsum[B*H*S];                  // sum of exp per row
__device__ float g_attnv[B*S*D];                   // attn @ V, (b,s, h*64+d)
__device__ float g_wt[D*NB*H];                     // Wcoef transposed: [d][n*8+h]

__device__ __forceinline__ float to_tf32(float x) {
    asm("cvt.rna.tf32.f32 %0, %1;" : "=f"(x) : "f"(x));
    return x;
}

// ---------------- tf32 wmma GEMM:  C = A(MxK) @ W(KxN) + bias ----------------
#define GT_ALD 36
#define GT_WLD 132
__global__ __launch_bounds__(256) void gemm_bias_tc(
    const float* __restrict__ A, const float* __restrict__ W,
    const float* __restrict__ bias, float* __restrict__ C,
    int M, int N, int K)
{
    __shared__ float As[128*GT_ALD];   // [m][k]
    __shared__ float Ws[32*GT_WLD];    // [k][n]
    __shared__ float Bt[16*GT_WLD];    // bias tile (rows identical)
    const int bm = blockIdx.y * 128, bn = blockIdx.x * 128;
    const int tid = threadIdx.x, w = tid >> 5;
    const int wm = (w >> 1) * 32, wn = (w & 1) * 64;

    for (int i = tid; i < 16*128; i += 256) {
        int r = i >> 7, c = i & 127;
        Bt[r*GT_WLD + c] = bias[bn + c];
    }
    __syncthreads();

    wmma::fragment<wmma::accumulator, 16,16,8, float> acc[2][4];
    #pragma unroll
    for (int i = 0; i < 2; i++)
        #pragma unroll
        for (int j = 0; j < 4; j++)
            wmma::load_matrix_sync(acc[i][j], Bt + wn + j*16, GT_WLD, wmma::mem_row_major);

    for (int k0 = 0; k0 < K; k0 += 32) {
        #pragma unroll
        for (int i = 0; i < 4; i++) {
            int id = i*256 + tid;
            int row = id >> 3, kc = (id & 7) * 4;
            float4 v = *(const float4*)&A[(size_t)(bm + row) * K + k0 + kc];
            v.x = to_tf32(v.x); v.y = to_tf32(v.y);
            v.z = to_tf32(v.z); v.w = to_tf32(v.w);
            *(float4*)&As[row*GT_ALD + kc] = v;
        }
        #pragma unroll
        for (int i = 0; i < 4; i++) {
            int id = i*256 + tid;
            int kr = id >> 5, nc = (id & 31) * 4;
            float4 v = *(const float4*)&W[(size_t)(k0 + kr) * N + bn + nc];
            v.x = to_tf32(v.x); v.y = to_tf32(v.y);
            v.z = to_tf32(v.z); v.w = to_tf32(v.w);
            *(float4*)&Ws[kr*GT_WLD + nc] = v;
        }
        __syncthreads();
        #pragma unroll
        for (int ks = 0; ks < 4; ks++) {
            wmma::fragment<wmma::matrix_a, 16,16,8, wmma::precision::tf32, wmma::row_major> a0, a1;
            wmma::load_matrix_sync(a0, As + wm*GT_ALD + ks*8, GT_ALD);
            wmma::load_matrix_sync(a1, As + (wm+16)*GT_ALD + ks*8, GT_ALD);
            #pragma unroll
            for (int j = 0; j < 4; j++) {
                wmma::fragment<wmma::matrix_b, 16,16,8, wmma::precision::tf32, wmma::row_major> bf;
                wmma::load_matrix_sync(bf, Ws + (ks*8)*GT_WLD + wn + j*16, GT_WLD);
                wmma::mma_sync(acc[0][j], a0, bf, acc[0][j]);
                wmma::mma_sync(acc[1][j], a1, bf, acc[1][j]);
            }
        }
        __syncthreads();
    }
    #pragma unroll
    for (int i = 0; i < 2; i++)
        #pragma unroll
        for (int j = 0; j < 4; j++)
            wmma::store_matrix_sync(C + (size_t)(bm + wm + i*16) * N + bn + wn + j*16,
                                    acc[i][j], N, wmma::mem_row_major);
}

// ---------------- Wcoef transpose + V half-convert ---------------------------
__global__ void transw_kernel(const float* __restrict__ Wcoef)
{
    int i = blockIdx.x * 256 + threadIdx.x;          // 40960 total
    if (i < D*NB*H) {
        int n = i / (D*H), rem = i % (D*H);
        int d = rem / H, h = rem % H;
        g_wt[d*(NB*H) + n*H + h] = Wcoef[i];
    }
}

__global__ void vconv_kernel()
{
    int i = blockIdx.x * 256 + threadIdx.x;          // over float4s: B*S*D/4
    float4 v = *(const float4*)&g_vp[i*4];
    __half2 h2[2];
    h2[0] = __floats2half2_rn(v.x, v.y);
    h2[1] = __floats2half2_rn(v.z, v.w);
    *(uint2*)&g_vph[i*4] = *(uint2*)h2;
}

// ---------------- coef: (B*S x 512) @ (512 x 80) ------------------------------
__global__ void coef_kernel(const float* __restrict__ bcoef)
{
    __shared__ float qsm[16*33];
    __shared__ float wsm[32*80];
    const int bm = blockIdx.x * 16;
    const int t = threadIdx.x;
    const int r = t & 15;             // row within tile
    const int cg = t >> 4;            // col group: 5 cols each (16 groups)
    float acc[5] = {};
    for (int k0 = 0; k0 < D; k0 += 32) {
        #pragma unroll
        for (int i = 0; i < 2; i++) {
            int idx = i*256 + t;
            int rr = idx >> 5, cc = idx & 31;
            qsm[rr*33 + cc] = g_qp[(size_t)(bm + rr) * D + k0 + cc];
        }
        #pragma unroll
        for (int i = 0; i < 3; i++) {
            int idx = i*256 + t;
            if (idx < 640)
                *(float4*)&wsm[idx*4] = *(const float4*)&g_wt[k0*80 + idx*4];
        }
        __syncthreads();
        #pragma unroll 8
        for (int kk = 0; kk < 32; kk++) {
            float a = qsm[r*33 + kk];
            #pragma unroll
            for (int j = 0; j < 5; j++)
                acc[j] += a * wsm[kk*80 + cg*5 + j];
        }
        __syncthreads();
    }
    const int rg = bm + r;
    const int b = rg >> 11, s = rg & (S-1);
    #pragma unroll
    for (int j = 0; j < 5; j++) {
        int nh = cg*5 + j;
        int n = nh >> 3, h = nh & 7;
        float v = acc[j] + bcoef[nh];
        if (n == 1) v = fabsf(v);
        g_coef[(((size_t)n*B + b)*H + h)*S + s] = 0.0125f * v;   // 0.1 / sqrt(64)
    }
}

// ---------------- fused basis + coef-dot + QK^T + exp + rowsum ---------------
// One head per block. grid: (B*H, S/64, S/64) — bh innermost keeps xdiff L2-hot.
// Writes exp(logit) to g_e (fp16) and atomically accumulates fp32 row sums.
#define QK_LD  68
#define LG_SMEM ((3*64*QK_LD + NB*64) * 4)
__global__ __launch_bounds__(256) void logits_kernel(const float* __restrict__ xdiff)
{
    extern __shared__ float sm[];
    float* qs  = sm;                          // 64*68 (pre-scaled by 0.125, tf32)
    float* ks  = qs + 64*QK_LD;               // 64*68 (tf32)
    float* ct  = ks + 64*QK_LD;               // 64*68 basis-init / C tile
    float* cf  = ct + 64*QK_LD;               // 10*64

    const int bh = blockIdx.x, b = bh >> 3, h = bh & 7;
    const int k0 = blockIdx.y * 64, q0 = blockIdx.z * 64;
    const int tid = threadIdx.x;
    const int w = tid >> 5;
    const int wr = w >> 1, wc = w & 1;        // 4x2 warp grid over 64x64

    // each thread owns 16 cells: row dq, k strip of 16
    const int dq = tid >> 2;
    const int dk = (tid & 3) * 16;

    // tile loads
    for (int idx = tid; idx < 64*16; idx += 256) {
        int q = idx >> 4, c = (idx & 15) * 4;
        float4 v = *(const float4*)&g_qp[((size_t)b*S + q0 + q) * D + h*DH + c];
        qs[q*QK_LD+c]   = to_tf32(0.125f*v.x);
        qs[q*QK_LD+c+1] = to_tf32(0.125f*v.y);
        qs[q*QK_LD+c+2] = to_tf32(0.125f*v.z);
        qs[q*QK_LD+c+3] = to_tf32(0.125f*v.w);
    }
    for (int idx = tid; idx < 64*16; idx += 256) {
        int k = idx >> 4, c = (idx & 15) * 4;
        float4 v = *(const float4*)&g_kp[((size_t)b*S + k0 + k) * D + h*DH + c];
        ks[k*QK_LD+c]   = to_tf32(v.x);
        ks[k*QK_LD+c+1] = to_tf32(v.y);
        ks[k*QK_LD+c+2] = to_tf32(v.z);
        ks[k*QK_LD+c+3] = to_tf32(v.w);
    }
    for (int idx = tid; idx < NB*64; idx += 256) {
        int n = idx >> 6, q = idx & 63;
        cf[idx] = g_coef[(((size_t)n*B + b)*H + h)*S + q0 + q];
    }
    __syncthreads();

    // basis ladder + 10-term dot (fp32) -> ct
    {
        float c0 = cf[0*64 + dq], c1f = -0.5f * cf[1*64 + dq];
        float c2 = cf[2*64 + dq], c3 = cf[3*64 + dq];
        float c4 = cf[4*64 + dq], c5 = cf[5*64 + dq];
        float c6 = cf[6*64 + dq], c7 = cf[7*64 + dq];
        float c8 = cf[8*64 + dq], c9 = cf[9*64 + dq];
        const float* xp = &xdiff[((size_t)b*S + q0 + dq) * S + k0 + dk];
        #pragma unroll
        for (int j4 = 0; j4 < 4; j4++) {
            float4 x4 = *(const float4*)&xp[j4*4];
            float xv[4] = {x4.x, x4.y, x4.z, x4.w};
            float o[4];
            #pragma unroll
            for (int u = 0; u < 4; u++) {
                float x = xv[u];
                float t = fmaf(-2.f, rintf(0.5f * x), x);   // period-2 reduction
                float s1, cc1;
                __sincosf(PI_F * t, &s1, &cc1);
                float tc2 = 2.f * fmaf(-2.f*s1, s1, 1.f);   // 2*cos(2 pi x)
                float s3 = fmaf(tc2, s1,  s1),  cc3 = fmaf(tc2, cc1, -cc1);
                float s5 = fmaf(tc2, s3, -s1),  cc5 = fmaf(tc2, cc3, -cc1);
                float s7 = fmaf(tc2, s5, -s3),  cc7 = fmaf(tc2, cc5, -cc3);
                float s9 = fmaf(tc2, s7, -s5),  cc9 = fmaf(tc2, cc7, -cc5);
                float a = c0 * x;
                a = fmaf(c1f, x*x, a);
                a = fmaf(c2, s1, a);  a = fmaf(c3, cc1, a);
                a = fmaf(c4, s3, a);  a = fmaf(c5, cc3, a);
                a = fmaf(c6, s5, a);  a = fmaf(c7, cc5, a);
                a = fmaf(c8, s9, a);  a = fmaf(c9, cc9, a);
                o[u] = a;
            }
            *(float4*)&ct[dq*QK_LD + dk + j4*4] = make_float4(o[0], o[1], o[2], o[3]);
        }
    }
    __syncthreads();

    // wmma: C(16x32 per warp) = basis_init + (0.125*Q) K^T  -> back to smem ct
    {
        wmma::fragment<wmma::accumulator, 16,16,8, float> c0, c1;
        wmma::load_matrix_sync(c0, ct + wr*16*QK_LD + wc*32,      QK_LD, wmma::mem_row_major);
        wmma::load_matrix_sync(c1, ct + wr*16*QK_LD + wc*32 + 16, QK_LD, wmma::mem_row_major);
        #pragma unroll
        for (int d0 = 0; d0 < DH; d0 += 8) {
            wmma::fragment<wmma::matrix_a, 16,16,8, wmma::precision::tf32, wmma::row_major> af;
            wmma::fragment<wmma::matrix_b, 16,16,8, wmma::precision::tf32, wmma::col_major> b0, b1;
            wmma::load_matrix_sync(af, qs + wr*16*QK_LD + d0, QK_LD);
            wmma::load_matrix_sync(b0, ks + (wc*32)*QK_LD + d0, QK_LD);
            wmma::load_matrix_sync(b1, ks + (wc*32+16)*QK_LD + d0, QK_LD);
            wmma::mma_sync(c0, af, b0, c0);
            wmma::mma_sync(c1, af, b1, c1);
        }
        __syncthreads();   // done reading ct as init
        wmma::store_matrix_sync(ct + wr*16*QK_LD + wc*32,      c0, QK_LD, wmma::mem_row_major);
        wmma::store_matrix_sync(ct + wr*16*QK_LD + wc*32 + 16, c1, QK_LD, wmma::mem_row_major);
    }
    __syncthreads();

    // exp, partial row-sum (atomic), write e (fp16) to g_e
    {
        float ssum = 0.f;
        __half* orow = &g_e[((size_t)bh*S + q0 + dq) * S + k0 + dk];
        #pragma unroll
        for (int j4 = 0; j4 < 4; j4++) {
            float4 v = *(const float4*)&ct[dq*QK_LD + dk + j4*4];
            v.x = __expf(v.x); v.y = __expf(v.y);
            v.z = __expf(v.z); v.w = __expf(v.w);
            ssum += v.x + v.y + v.z + v.w;
            __half2 h2[2];
            h2[0] = __floats2half2_rn(v.x, v.y);
            h2[1] = __floats2half2_rn(v.z, v.w);
            *(uint2*)&orow[j4*4] = *(uint2*)h2;
        }
        ssum += __shfl_xor_sync(0xffffffffu, ssum, 1);
        ssum += __shfl_xor_sync(0xffffffffu, ssum, 2);
        if ((tid & 3) == 0)
            atomicAdd(&g_rowsum[(size_t)bh*S + q0 + dq], ssum);
    }
}

// ---------------- fused normalize + PV (fp16 wmma, single pass) --------------
#define SPH_LD 72
__global__ __launch_bounds__(256) void softpv_kernel(float* __restrict__ attn)
{
    __shared__ __half pt[64*SPH_LD];
    __shared__ __half vt[64*SPH_LD];
    const int b = blockIdx.z, h = blockIdx.y;
    const int q0 = blockIdx.x * 64;
    const int tid = threadIdx.x;
    const int r  = tid >> 2, tq = tid & 3;    // 64 rows x 4 threads
    const int w = tid >> 5;
    const int wr = w >> 1, wc = w & 1;        // 4x2 warps: 16q x 32d each

    const size_t rowbase = ((size_t)(b*H + h)*S + q0) * S;
    const __half* erow = g_e + rowbase + (size_t)r * S;
    const float riz = 1.f / g_rowsum[(size_t)(b*H + h)*S + q0 + r];

    wmma::fragment<wmma::accumulator, 16,16,16, float> acc[2];
    wmma::fill_fragment(acc[0], 0.f);
    wmma::fill_fragment(acc[1], 0.f);

    float* arow = attn + rowbase + (size_t)r * S;
    for (int k0 = 0; k0 < S; k0 += 64) {
        // V tile (64k x 64d) from half buffer — straight copy
        #pragma unroll
        for (int i = 0; i < 4; i++) {
            int idx = i*256 + tid;                    // uint2 (4 halves) units
            int k = idx >> 4, c = (idx & 15) * 4;
            *(uint2*)&vt[k*SPH_LD + c] =
                *(const uint2*)&g_vph[((size_t)b*S + k0 + k)*D + h*DH + c];
        }
        // p tile: e(half) * riz -> attn (fp32) + pt (half)
        {
            const __half2* ep = (const __half2*)(erow + k0 + tq*16);
            #pragma unroll
            for (int j = 0; j < 4; j++) {
                __half2 e0 = ep[2*j], e1 = ep[2*j+1];
                float2 f0 = __half22float2(e0), f1 = __half22float2(e1);
                f0.x *= riz; f0.y *= riz; f1.x *= riz; f1.y *= riz;
                *(float4*)&arow[k0 + tq*16 + j*4] = make_float4(f0.x, f0.y, f1.x, f1.y);
                __half2 h2[2];
                h2[0] = __floats2half2_rn(f0.x, f0.y);
                h2[1] = __floats2half2_rn(f1.x, f1.y);
                *(uint2*)&pt[r*SPH_LD + tq*16 + j*4] = *(uint2*)h2;
            }
        }
        __syncthreads();
        #pragma unroll
        for (int ch = 0; ch < 4; ch++) {
            wmma::fragment<wmma::matrix_a, 16,16,16, __half, wmma::row_major> af;
            wmma::load_matrix_sync(af, pt + wr*16*SPH_LD + ch*16, SPH_LD);
            #pragma unroll
            for (int nb = 0; nb < 2; nb++) {
                wmma::fragment<wmma::matrix_b, 16,16,16, __half, wmma::row_major> bf;
                wmma::load_matrix_sync(bf, vt + (ch*16)*SPH_LD + wc*32 + nb*16, SPH_LD);
                wmma::mma_sync(acc[nb], af, bf, acc[nb]);
            }
        }
        __syncthreads();
    }
    #pragma unroll
    for (int nb = 0; nb < 2; nb++) {
        float* o = &g_attnv[((size_t)b*S + q0 + wr*16)*D + h*DH + wc*32 + nb*16];
        wmma::store_matrix_sync(o, acc[nb], D, wmma::mem_row_major);
    }
}

// -----------------------------------------------------------------------------
extern "C" void kernel_launch(void* const* d_in, const int* in_sizes, int n_in,
                              void* d_out, int out_size)
{
    const float* q     = (const float*)d_in[0];
    const float* k     = (const float*)d_in[1];
    const float* v     = (const float*)d_in[2];
    const float* xdiff = (const float*)d_in[3];
    const float* Wq    = (const float*)d_in[4];
    const float* bq    = (const float*)d_in[5];
    const float* Wk    = (const float*)d_in[6];
    const float* bk    = (const float*)d_in[7];
    const float* Wv    = (const float*)d_in[8];
    const float* bv    = (const float*)d_in[9];
    const float* Wcoef = (const float*)d_in[10];
    const float* bcoef = (const float*)d_in[11];
    const float* Wo    = (const float*)d_in[12];
    const float* bo    = (const float*)d_in[13];
    float* out = (float*)d_out;                       // [B*S*D] out | [B*H*S*S] attn
    float* attn = out + (size_t)B*S*D;

    float *qp, *kp, *vp, *av, *rs;
    cudaGetSymbolAddress((void**)&qp, g_qp);
    cudaGetSymbolAddress((void**)&kp, g_kp);
    cudaGetSymbolAddress((void**)&vp, g_vp);
    cudaGetSymbolAddress((void**)&av, g_attnv);
    cudaGetSymbolAddress((void**)&rs, g_rowsum);

    cudaFuncSetAttribute(logits_kernel, cudaFuncAttributeMaxDynamicSharedMemorySize, LG_SMEM);

    cudaMemsetAsync(rs, 0, (size_t)B*H*S*sizeof(float), 0);

    dim3 ggrid(D/128, (B*S)/128);
    gemm_bias_tc<<<ggrid, 256>>>(q, Wq, bq, qp, B*S, D, D);
    gemm_bias_tc<<<ggrid, 256>>>(k, Wk, bk, kp, B*S, D, D);
    gemm_bias_tc<<<ggrid, 256>>>(v, Wv, bv, vp, B*S, D, D);

    transw_kernel<<<(D*NB*H + 255)/256, 256>>>(Wcoef);
    vconv_kernel<<<(B*S*D/4 + 255)/256, 256>>>();
    coef_kernel<<<(B*S)/16, 256>>>(bcoef);

    logits_kernel<<<dim3(B*H, S/64, S/64), 256, LG_SMEM>>>(xdiff);

    softpv_kernel<<<dim3(S/64, H, B), 256>>>(attn);

    gemm_bias_tc<<<ggrid, 256>>>(av, Wo, bo, out, B*S, D, D);
}

// round 9
// speedup vs baseline: 1.6602x; 1.2035x over previous
#include <cuda_runtime.h>
#include <cuda_fp16.h>
#include <mma.h>
#include <math.h>

using namespace nvcuda;

#define B 2
#define S 2048
#define D 512
#define H 8
#define DH 64
#define NB 10
#define PI_F 3.14159265358979323846f

// ---------------- scratch ----------------------------------------------------
__device__ float g_qp[B*S*D];
__device__ float g_kp[B*S*D];
__device__ float g_vp[B*S*D];
__device__ __half g_qph[B*S*D];                    // half qp, pre-scaled 0.125
__device__ __half g_kph[B*S*D];                    // half kp
__device__ __half g_vph[B*S*D];                    // half vp
__device__ float g_coef[NB*B*H*S];                 // [n][b][h][s], pre-scaled by 0.1/8
__device__ __half g_e[(size_t)B*H*S*S];            // exp(logit) in fp16 (134 MB)
__device__ float g_rowsum[B*H*S];                  // sum of exp per row
__device__ float g_attnv[B*S*D];                   // attn @ V, (b,s, h*64+d)
__device__ float g_wt[D*NB*H];                     // Wcoef transposed: [d][n*8+h]

__device__ __forceinline__ float to_tf32(float x) {
    asm("cvt.rna.tf32.f32 %0, %1;" : "=f"(x) : "f"(x));
    return x;
}

// ---------------- tf32 wmma GEMM:  C = A(MxK) @ W(KxN) + bias ----------------
// block tile 128(M) x 64(N), 256 threads (8 warps 4x2, warp 32x32).
// grid (N/64, M/128) = (8, 32) = 256 blocks -> full chip.
#define GT_ALD 36
#define GT_WLD 68
__global__ __launch_bounds__(256) void gemm_bias_tc(
    const float* __restrict__ A, const float* __restrict__ W,
    const float* __restrict__ bias, float* __restrict__ C,
    int M, int N, int K)
{
    __shared__ float As[128*GT_ALD];   // [m][k] k-chunk 32
    __shared__ float Ws[32*GT_WLD];    // [k][n]
    __shared__ float Bt[16*GT_WLD];    // bias tile (rows identical)
    const int bm = blockIdx.y * 128, bn = blockIdx.x * 64;
    const int tid = threadIdx.x, w = tid >> 5;
    const int wm = (w >> 1) * 32, wn = (w & 1) * 32;

    for (int i = tid; i < 16*64; i += 256) {
        int r = i >> 6, c = i & 63;
        Bt[r*GT_WLD + c] = bias[bn + c];
    }
    __syncthreads();

    wmma::fragment<wmma::accumulator, 16,16,8, float> acc[2][2];
    #pragma unroll
    for (int i = 0; i < 2; i++)
        #pragma unroll
        for (int j = 0; j < 2; j++)
            wmma::load_matrix_sync(acc[i][j], Bt + wn + j*16, GT_WLD, wmma::mem_row_major);

    for (int k0 = 0; k0 < K; k0 += 32) {
        #pragma unroll
        for (int i = 0; i < 4; i++) {
            int id = i*256 + tid;
            int row = id >> 3, kc = (id & 7) * 4;
            float4 v = *(const float4*)&A[(size_t)(bm + row) * K + k0 + kc];
            v.x = to_tf32(v.x); v.y = to_tf32(v.y);
            v.z = to_tf32(v.z); v.w = to_tf32(v.w);
            *(float4*)&As[row*GT_ALD + kc] = v;
        }
        #pragma unroll
        for (int i = 0; i < 2; i++) {
            int id = i*256 + tid;
            int kr = id >> 4, nc = (id & 15) * 4;
            float4 v = *(const float4*)&W[(size_t)(k0 + kr) * N + bn + nc];
            v.x = to_tf32(v.x); v.y = to_tf32(v.y);
            v.z = to_tf32(v.z); v.w = to_tf32(v.w);
            *(float4*)&Ws[kr*GT_WLD + nc] = v;
        }
        __syncthreads();
        #pragma unroll
        for (int ks = 0; ks < 4; ks++) {
            wmma::fragment<wmma::matrix_a, 16,16,8, wmma::precision::tf32, wmma::row_major> a0, a1;
            wmma::load_matrix_sync(a0, As + wm*GT_ALD + ks*8, GT_ALD);
            wmma::load_matrix_sync(a1, As + (wm+16)*GT_ALD + ks*8, GT_ALD);
            wmma::fragment<wmma::matrix_b, 16,16,8, wmma::precision::tf32, wmma::row_major> b0, b1;
            wmma::load_matrix_sync(b0, Ws + (ks*8)*GT_WLD + wn, GT_WLD);
            wmma::load_matrix_sync(b1, Ws + (ks*8)*GT_WLD + wn + 16, GT_WLD);
            wmma::mma_sync(acc[0][0], a0, b0, acc[0][0]);
            wmma::mma_sync(acc[0][1], a0, b1, acc[0][1]);
            wmma::mma_sync(acc[1][0], a1, b0, acc[1][0]);
            wmma::mma_sync(acc[1][1], a1, b1, acc[1][1]);
        }
        __syncthreads();
    }
    #pragma unroll
    for (int i = 0; i < 2; i++)
        #pragma unroll
        for (int j = 0; j < 2; j++)
            wmma::store_matrix_sync(C + (size_t)(bm + wm + i*16) * N + bn + wn + j*16,
                                    acc[i][j], N, wmma::mem_row_major);
}

// ---------------- Wcoef transpose --------------------------------------------
__global__ void transw_kernel(const float* __restrict__ Wcoef)
{
    int i = blockIdx.x * 256 + threadIdx.x;          // 40960 total
    if (i < D*NB*H) {
        int n = i / (D*H), rem = i % (D*H);
        int d = rem / H, h = rem % H;
        g_wt[d*(NB*H) + n*H + h] = Wcoef[i];
    }
}

// ---------------- qp/kp/vp -> half copies (0.125 folded into q) ---------------
__global__ void qkvconv_kernel()
{
    int i = blockIdx.x * 256 + threadIdx.x;          // over float4s: B*S*D/4
    {
        float4 v = *(const float4*)&g_qp[i*4];
        __half2 h2[2];
        h2[0] = __floats2half2_rn(0.125f*v.x, 0.125f*v.y);
        h2[1] = __floats2half2_rn(0.125f*v.z, 0.125f*v.w);
        *(uint2*)&g_qph[i*4] = *(uint2*)h2;
    }
    {
        float4 v = *(const float4*)&g_kp[i*4];
        __half2 h2[2];
        h2[0] = __floats2half2_rn(v.x, v.y);
        h2[1] = __floats2half2_rn(v.z, v.w);
        *(uint2*)&g_kph[i*4] = *(uint2*)h2;
    }
    {
        float4 v = *(const float4*)&g_vp[i*4];
        __half2 h2[2];
        h2[0] = __floats2half2_rn(v.x, v.y);
        h2[1] = __floats2half2_rn(v.z, v.w);
        *(uint2*)&g_vph[i*4] = *(uint2*)h2;
    }
}

// ---------------- coef: (B*S x 512) @ (512 x 80) ------------------------------
__global__ void coef_kernel(const float* __restrict__ bcoef)
{
    __shared__ float qsm[16*33];
    __shared__ float wsm[32*80];
    const int bm = blockIdx.x * 16;
    const int t = threadIdx.x;
    const int r = t & 15;             // row within tile
    const int cg = t >> 4;            // col group: 5 cols each (16 groups)
    float acc[5] = {};
    for (int k0 = 0; k0 < D; k0 += 32) {
        #pragma unroll
        for (int i = 0; i < 2; i++) {
            int idx = i*256 + t;
            int rr = idx >> 5, cc = idx & 31;
            qsm[rr*33 + cc] = g_qp[(size_t)(bm + rr) * D + k0 + cc];
        }
        #pragma unroll
        for (int i = 0; i < 3; i++) {
            int idx = i*256 + t;
            if (idx < 640)
                *(float4*)&wsm[idx*4] = *(const float4*)&g_wt[k0*80 + idx*4];
        }
        __syncthreads();
        #pragma unroll 8
        for (int kk = 0; kk < 32; kk++) {
            float a = qsm[r*33 + kk];
            #pragma unroll
            for (int j = 0; j < 5; j++)
                acc[j] += a * wsm[kk*80 + cg*5 + j];
        }
        __syncthreads();
    }
    const int rg = bm + r;
    const int b = rg >> 11, s = rg & (S-1);
    #pragma unroll
    for (int j = 0; j < 5; j++) {
        int nh = cg*5 + j;
        int n = nh >> 3, h = nh & 7;
        float v = acc[j] + bcoef[nh];
        if (n == 1) v = fabsf(v);
        g_coef[(((size_t)n*B + b)*H + h)*S + s] = 0.0125f * v;   // 0.1 / sqrt(64)
    }
}

// ---------------- fused basis + coef-dot + QK^T(fp16) + exp + rowsum ---------
// One head per block. Epilogue (ladder + 10-term dot) in half2.
#define QK_LD  72                     // halves per row in qs/ks
#define CT_LD  68
// smem bytes: 2*64*72*2 (qs,ks) + 64*68*4 (ct) + 640*4 (cf) = 38400
#define LG_SMEM (2*64*QK_LD*2 + 64*CT_LD*4 + NB*64*4)
__global__ __launch_bounds__(256) void logits_kernel(const float* __restrict__ xdiff)
{
    extern __shared__ char smraw[];
    __half* qs = (__half*)smraw;                       // 64*72
    __half* ks = qs + 64*QK_LD;                        // 64*72
    float*  ct = (float*)(smraw + 2*64*QK_LD*2);       // 64*68
    float*  cf = ct + 64*CT_LD;                        // 10*64

    const int bh = blockIdx.x, b = bh >> 3, h = bh & 7;
    const int k0 = blockIdx.y * 64, q0 = blockIdx.z * 64;
    const int tid = threadIdx.x;
    const int w = tid >> 5;
    const int wr = w >> 1, wc = w & 1;        // 4x2 warp grid over 64x64

    // each thread owns 16 cells: row dq, k strip of 16
    const int dq = tid >> 2;
    const int dk = (tid & 3) * 16;

    // tile loads (half, 4 halves per uint2)
    for (int idx = tid; idx < 64*16; idx += 256) {
        int q = idx >> 4, c = (idx & 15) * 4;
        *(uint2*)&qs[q*QK_LD + c] =
            *(const uint2*)&g_qph[((size_t)b*S + q0 + q) * D + h*DH + c];
    }
    for (int idx = tid; idx < 64*16; idx += 256) {
        int k = idx >> 4, c = (idx & 15) * 4;
        *(uint2*)&ks[k*QK_LD + c] =
            *(const uint2*)&g_kph[((size_t)b*S + k0 + k) * D + h*DH + c];
    }
    for (int idx = tid; idx < NB*64; idx += 256) {
        int n = idx >> 6, q = idx & 63;
        cf[idx] = g_coef[(((size_t)n*B + b)*H + h)*S + q0 + q];
    }
    __syncthreads();

    // half2 ladder + 10-term dot -> ct (fp32)
    {
        half2 ch[10];
        #pragma unroll
        for (int n = 0; n < NB; n++) {
            float c = cf[n*64 + dq];
            if (n == 1) c = -0.5f * c;        // fold -0.5 x^2
            ch[n] = __float2half2_rn(c);
        }
        const half2 hm4 = __float2half2_rn(-4.f);
        const half2 h2c = __float2half2_rn(2.f);
        const float* xp = &xdiff[((size_t)b*S + q0 + dq) * S + k0 + dk];
        #pragma unroll
        for (int jp = 0; jp < 8; jp++) {
            float2 x2 = *(const float2*)&xp[2*jp];
            float t0 = fmaf(-2.f, rintf(0.5f * x2.x), x2.x);
            float t1 = fmaf(-2.f, rintf(0.5f * x2.y), x2.y);
            float s0f, c0f, s1f, c1f;
            __sincosf(PI_F * t0, &s0f, &c0f);
            __sincosf(PI_F * t1, &s1f, &c1f);
            half2 X  = __floats2half2_rn(x2.x, x2.y);
            half2 s1 = __floats2half2_rn(s0f, s1f);
            half2 c1 = __floats2half2_rn(c0f, c1f);
            half2 t2 = __hfma2(__hmul2(s1, s1), hm4, h2c);   // 2*cos(2 pi x)
            half2 s3 = __hfma2(t2, s1, s1);
            half2 c3 = __hfma2(t2, c1, __hneg2(c1));
            half2 s5 = __hfma2(t2, s3, __hneg2(s1));
            half2 c5 = __hfma2(t2, c3, __hneg2(c1));
            half2 s7 = __hfma2(t2, s5, __hneg2(s3));
            half2 c7 = __hfma2(t2, c5, __hneg2(c3));
            half2 s9 = __hfma2(t2, s7, __hneg2(s5));
            half2 c9 = __hfma2(t2, c7, __hneg2(c5));
            half2 a = __hmul2(ch[0], X);
            a = __hfma2(ch[1], __hmul2(X, X), a);
            a = __hfma2(ch[2], s1, a);  a = __hfma2(ch[3], c1, a);
            a = __hfma2(ch[4], s3, a);  a = __hfma2(ch[5], c3, a);
            a = __hfma2(ch[6], s5, a);  a = __hfma2(ch[7], c5, a);
            a = __hfma2(ch[8], s9, a);  a = __hfma2(ch[9], c9, a);
            float2 f = __half22float2(a);
            *(float2*)&ct[dq*CT_LD + dk + 2*jp] = f;
        }
    }
    __syncthreads();

    // fp16 wmma: C(16x32 per warp) = basis_init + (0.125*Q) K^T  -> back to ct
    {
        wmma::fragment<wmma::accumulator, 16,16,16, float> c0, c1;
        wmma::load_matrix_sync(c0, ct + wr*16*CT_LD + wc*32,      CT_LD, wmma::mem_row_major);
        wmma::load_matrix_sync(c1, ct + wr*16*CT_LD + wc*32 + 16, CT_LD, wmma::mem_row_major);
        #pragma unroll
        for (int d0 = 0; d0 < DH; d0 += 16) {
            wmma::fragment<wmma::matrix_a, 16,16,16, __half, wmma::row_major> af;
            wmma::fragment<wmma::matrix_b, 16,16,16, __half, wmma::col_major> b0, b1;
            wmma::load_matrix_sync(af, qs + wr*16*QK_LD + d0, QK_LD);
            wmma::load_matrix_sync(b0, ks + (wc*32)*QK_LD + d0, QK_LD);
            wmma::load_matrix_sync(b1, ks + (wc*32+16)*QK_LD + d0, QK_LD);
            wmma::mma_sync(c0, af, b0, c0);
            wmma::mma_sync(c1, af, b1, c1);
        }
        __syncthreads();   // done reading ct as init
        wmma::store_matrix_sync(ct + wr*16*CT_LD + wc*32,      c0, CT_LD, wmma::mem_row_major);
        wmma::store_matrix_sync(ct + wr*16*CT_LD + wc*32 + 16, c1, CT_LD, wmma::mem_row_major);
    }
    __syncthreads();

    // exp, partial row-sum (atomic), write e (fp16) to g_e
    {
        float ssum = 0.f;
        __half* orow = &g_e[((size_t)bh*S + q0 + dq) * S + k0 + dk];
        #pragma unroll
        for (int j4 = 0; j4 < 4; j4++) {
            float4 v = *(const float4*)&ct[dq*CT_LD + dk + j4*4];
            v.x = __expf(v.x); v.y = __expf(v.y);
            v.z = __expf(v.z); v.w = __expf(v.w);
            ssum += v.x + v.y + v.z + v.w;
            __half2 h2[2];
            h2[0] = __floats2half2_rn(v.x, v.y);
            h2[1] = __floats2half2_rn(v.z, v.w);
            *(uint2*)&orow[j4*4] = *(uint2*)h2;
        }
        ssum += __shfl_xor_sync(0xffffffffu, ssum, 1);
        ssum += __shfl_xor_sync(0xffffffffu, ssum, 2);
        if ((tid & 3) == 0)
            atomicAdd(&g_rowsum[(size_t)bh*S + q0 + dq], ssum);
    }
}

// ---------------- fused normalize + PV (fp16 wmma, single pass) --------------
#define SPH_LD 72
__global__ __launch_bounds__(256) void softpv_kernel(float* __restrict__ attn)
{
    __shared__ __half pt[64*SPH_LD];
    __shared__ __half vt[64*SPH_LD];
    const int b = blockIdx.z, h = blockIdx.y;
    const int q0 = blockIdx.x * 64;
    const int tid = threadIdx.x;
    const int r  = tid >> 2, tq = tid & 3;    // 64 rows x 4 threads
    const int w = tid >> 5;
    const int wr = w >> 1, wc = w & 1;        // 4x2 warps: 16q x 32d each

    const size_t rowbase = ((size_t)(b*H + h)*S + q0) * S;
    const __half* erow = g_e + rowbase + (size_t)r * S;
    const float riz = 1.f / g_rowsum[(size_t)(b*H + h)*S + q0 + r];

    wmma::fragment<wmma::accumulator, 16,16,16, float> acc[2];
    wmma::fill_fragment(acc[0], 0.f);
    wmma::fill_fragment(acc[1], 0.f);

    float* arow = attn + rowbase + (size_t)r * S;
    for (int k0 = 0; k0 < S; k0 += 64) {
        // V tile (64k x 64d) from half buffer — straight copy
        #pragma unroll
        for (int i = 0; i < 4; i++) {
            int idx = i*256 + tid;                    // uint2 (4 halves) units
            int k = idx >> 4, c = (idx & 15) * 4;
            *(uint2*)&vt[k*SPH_LD + c] =
                *(const uint2*)&g_vph[((size_t)b*S + k0 + k)*D + h*DH + c];
        }
        // p tile: e(half) * riz -> attn (fp32) + pt (half)
        {
            const __half2* ep = (const __half2*)(erow + k0 + tq*16);
            #pragma unroll
            for (int j = 0; j < 4; j++) {
                __half2 e0 = ep[2*j], e1 = ep[2*j+1];
                float2 f0 = __half22float2(e0), f1 = __half22float2(e1);
                f0.x *= riz; f0.y *= riz; f1.x *= riz; f1.y *= riz;
                *(float4*)&arow[k0 + tq*16 + j*4] = make_float4(f0.x, f0.y, f1.x, f1.y);
                __half2 h2[2];
                h2[0] = __floats2half2_rn(f0.x, f0.y);
                h2[1] = __floats2half2_rn(f1.x, f1.y);
                *(uint2*)&pt[r*SPH_LD + tq*16 + j*4] = *(uint2*)h2;
            }
        }
        __syncthreads();
        #pragma unroll
        for (int ch = 0; ch < 4; ch++) {
            wmma::fragment<wmma::matrix_a, 16,16,16, __half, wmma::row_major> af;
            wmma::load_matrix_sync(af, pt + wr*16*SPH_LD + ch*16, SPH_LD);
            #pragma unroll
            for (int nb = 0; nb < 2; nb++) {
                wmma::fragment<wmma::matrix_b, 16,16,16, __half, wmma::row_major> bf;
                wmma::load_matrix_sync(bf, vt + (ch*16)*SPH_LD + wc*32 + nb*16, SPH_LD);
                wmma::mma_sync(acc[nb], af, bf, acc[nb]);
            }
        }
        __syncthreads();
    }
    #pragma unroll
    for (int nb = 0; nb < 2; nb++) {
        float* o = &g_attnv[((size_t)b*S + q0 + wr*16)*D + h*DH + wc*32 + nb*16];
        wmma::store_matrix_sync(o, acc[nb], D, wmma::mem_row_major);
    }
}

// -----------------------------------------------------------------------------
extern "C" void kernel_launch(void* const* d_in, const int* in_sizes, int n_in,
                              void* d_out, int out_size)
{
    const float* q     = (const float*)d_in[0];
    const float* k     = (const float*)d_in[1];
    const float* v     = (const float*)d_in[2];
    const float* xdiff = (const float*)d_in[3];
    const float* Wq    = (const float*)d_in[4];
    const float* bq    = (const float*)d_in[5];
    const float* Wk    = (const float*)d_in[6];
    const float* bk    = (const float*)d_in[7];
    const float* Wv    = (const float*)d_in[8];
    const float* bv    = (const float*)d_in[9];
    const float* Wcoef = (const float*)d_in[10];
    const float* bcoef = (const float*)d_in[11];
    const float* Wo    = (const float*)d_in[12];
    const float* bo    = (const float*)d_in[13];
    float* out = (float*)d_out;                       // [B*S*D] out | [B*H*S*S] attn
    float* attn = out + (size_t)B*S*D;

    float *qp, *kp, *vp, *av, *rs;
    cudaGetSymbolAddress((void**)&qp, g_qp);
    cudaGetSymbolAddress((void**)&kp, g_kp);
    cudaGetSymbolAddress((void**)&vp, g_vp);
    cudaGetSymbolAddress((void**)&av, g_attnv);
    cudaGetSymbolAddress((void**)&rs, g_rowsum);

    cudaFuncSetAttribute(logits_kernel, cudaFuncAttributeMaxDynamicSharedMemorySize, LG_SMEM);

    cudaMemsetAsync(rs, 0, (size_t)B*H*S*sizeof(float), 0);

    dim3 ggrid(D/64, (B*S)/128);
    gemm_bias_tc<<<ggrid, 256>>>(q, Wq, bq, qp, B*S, D, D);
    gemm_bias_tc<<<ggrid, 256>>>(k, Wk, bk, kp, B*S, D, D);
    gemm_bias_tc<<<ggrid, 256>>>(v, Wv, bv, vp, B*S, D, D);

    transw_kernel<<<(D*NB*H + 255)/256, 256>>>(Wcoef);
    qkvconv_kernel<<<(B*S*D/4)/256, 256>>>();
    coef_kernel<<<(B*S)/16, 256>>>(bcoef);

    logits_kernel<<<dim3(B*H, S/64, S/64), 256, LG_SMEM>>>(xdiff);

    softpv_kernel<<<dim3(S/64, H, B), 256>>>(attn);

    gemm_bias_tc<<<ggrid, 256>>>(av, Wo, bo, out, B*S, D, D);
}

// round 11
// speedup vs baseline: 1.8390x; 1.1077x over previous
#include <cuda_runtime.h>
#include <cuda_fp16.h>
#include <mma.h>
#include <math.h>
#include <stdint.h>

using namespace nvcuda;
typedef unsigned int u32;

#define B 2
#define S 2048
#define D 512
#define H 8
#define DH 64
#define NB 10
#define PI_F 3.14159265358979323846f

// ---------------- scratch ----------------------------------------------------
__device__ float g_qp[B*S*D];
__device__ float g_kp[B*S*D];
__device__ float g_vp[B*S*D];
__device__ __half g_qph[B*S*D];                    // half qp, pre-scaled 0.125
__device__ __half g_kph[B*S*D];                    // half kp
__device__ __half g_vph[B*S*D];                    // half vp
__device__ float g_coef[NB*B*H*S];                 // [n][b][h][s], pre-scaled by 0.1/8
__device__ __half g_e[(size_t)B*H*S*S];            // exp(logit) in fp16 (134 MB)
__device__ float g_rowsum[B*H*S];                  // sum of exp per row
__device__ float g_attnv[B*S*D];                   // attn @ V, (b,s, h*64+d)
__device__ float g_wt[D*NB*H];                     // Wcoef transposed: [d][n*8+h]

__device__ __forceinline__ float to_tf32(float x) {
    asm("cvt.rna.tf32.f32 %0, %1;" : "=f"(x) : "f"(x));
    return x;
}
__device__ __forceinline__ u32 sptr(const void* p) {
    return (u32)__cvta_generic_to_shared(p);
}
__device__ __forceinline__ void ldsm4(u32& r0, u32& r1, u32& r2, u32& r3, u32 addr) {
    asm volatile("ldmatrix.sync.aligned.m8n8.x4.shared.b16 {%0,%1,%2,%3}, [%4];"
        : "=r"(r0), "=r"(r1), "=r"(r2), "=r"(r3) : "r"(addr));
}
__device__ __forceinline__ void mma16816(float* d, u32 a0, u32 a1, u32 a2,
                                         u32 a3, u32 b0, u32 b1) {
    asm volatile("mma.sync.aligned.m16n8k16.row.col.f32.f16.f16.f32 "
        "{%0,%1,%2,%3}, {%4,%5,%6,%7}, {%8,%9}, {%0,%1,%2,%3};"
        : "+f"(d[0]), "+f"(d[1]), "+f"(d[2]), "+f"(d[3])
        : "r"(a0), "r"(a1), "r"(a2), "r"(a3), "r"(b0), "r"(b1));
}

// ---------------- tf32 wmma GEMM:  C = A(MxK) @ W(KxN) + bias ----------------
#define GT_ALD 36
#define GT_WLD 68
__global__ __launch_bounds__(256) void gemm_bias_tc(
    const float* __restrict__ A, const float* __restrict__ W,
    const float* __restrict__ bias, float* __restrict__ C,
    int M, int N, int K)
{
    __shared__ float As[128*GT_ALD];   // [m][k] k-chunk 32
    __shared__ float Ws[32*GT_WLD];    // [k][n]
    __shared__ float Bt[16*GT_WLD];    // bias tile (rows identical)
    const int bm = blockIdx.y * 128, bn = blockIdx.x * 64;
    const int tid = threadIdx.x, w = tid >> 5;
    const int wm = (w >> 1) * 32, wn = (w & 1) * 32;

    for (int i = tid; i < 16*64; i += 256) {
        int r = i >> 6, c = i & 63;
        Bt[r*GT_WLD + c] = bias[bn + c];
    }
    __syncthreads();

    wmma::fragment<wmma::accumulator, 16,16,8, float> acc[2][2];
    #pragma unroll
    for (int i = 0; i < 2; i++)
        #pragma unroll
        for (int j = 0; j < 2; j++)
            wmma::load_matrix_sync(acc[i][j], Bt + wn + j*16, GT_WLD, wmma::mem_row_major);

    for (int k0 = 0; k0 < K; k0 += 32) {
        #pragma unroll
        for (int i = 0; i < 4; i++) {
            int id = i*256 + tid;
            int row = id >> 3, kc = (id & 7) * 4;
            float4 v = *(const float4*)&A[(size_t)(bm + row) * K + k0 + kc];
            v.x = to_tf32(v.x); v.y = to_tf32(v.y);
            v.z = to_tf32(v.z); v.w = to_tf32(v.w);
            *(float4*)&As[row*GT_ALD + kc] = v;
        }
        #pragma unroll
        for (int i = 0; i < 2; i++) {
            int id = i*256 + tid;
            int kr = id >> 4, nc = (id & 15) * 4;
            float4 v = *(const float4*)&W[(size_t)(k0 + kr) * N + bn + nc];
            v.x = to_tf32(v.x); v.y = to_tf32(v.y);
            v.z = to_tf32(v.z); v.w = to_tf32(v.w);
            *(float4*)&Ws[kr*GT_WLD + nc] = v;
        }
        __syncthreads();
        #pragma unroll
        for (int ks = 0; ks < 4; ks++) {
            wmma::fragment<wmma::matrix_a, 16,16,8, wmma::precision::tf32, wmma::row_major> a0, a1;
            wmma::load_matrix_sync(a0, As + wm*GT_ALD + ks*8, GT_ALD);
            wmma::load_matrix_sync(a1, As + (wm+16)*GT_ALD + ks*8, GT_ALD);
            wmma::fragment<wmma::matrix_b, 16,16,8, wmma::precision::tf32, wmma::row_major> b0, b1;
            wmma::load_matrix_sync(b0, Ws + (ks*8)*GT_WLD + wn, GT_WLD);
            wmma::load_matrix_sync(b1, Ws + (ks*8)*GT_WLD + wn + 16, GT_WLD);
            wmma::mma_sync(acc[0][0], a0, b0, acc[0][0]);
            wmma::mma_sync(acc[0][1], a0, b1, acc[0][1]);
            wmma::mma_sync(acc[1][0], a1, b0, acc[1][0]);
            wmma::mma_sync(acc[1][1], a1, b1, acc[1][1]);
        }
        __syncthreads();
    }
    #pragma unroll
    for (int i = 0; i < 2; i++)
        #pragma unroll
        for (int j = 0; j < 2; j++)
            wmma::store_matrix_sync(C + (size_t)(bm + wm + i*16) * N + bn + wn + j*16,
                                    acc[i][j], N, wmma::mem_row_major);
}

// ---------------- Wcoef transpose --------------------------------------------
__global__ void transw_kernel(const float* __restrict__ Wcoef)
{
    int i = blockIdx.x * 256 + threadIdx.x;          // 40960 total
    if (i < D*NB*H) {
        int n = i / (D*H), rem = i % (D*H);
        int d = rem / H, h = rem % H;
        g_wt[d*(NB*H) + n*H + h] = Wcoef[i];
    }
}

// ---------------- qp/kp/vp -> half copies (0.125 folded into q) ---------------
__global__ void qkvconv_kernel()
{
    int i = blockIdx.x * 256 + threadIdx.x;          // over float4s: B*S*D/4
    {
        float4 v = *(const float4*)&g_qp[i*4];
        __half2 h2[2];
        h2[0] = __floats2half2_rn(0.125f*v.x, 0.125f*v.y);
        h2[1] = __floats2half2_rn(0.125f*v.z, 0.125f*v.w);
        *(uint2*)&g_qph[i*4] = *(uint2*)h2;
    }
    {
        float4 v = *(const float4*)&g_kp[i*4];
        __half2 h2[2];
        h2[0] = __floats2half2_rn(v.x, v.y);
        h2[1] = __floats2half2_rn(v.z, v.w);
        *(uint2*)&g_kph[i*4] = *(uint2*)h2;
    }
    {
        float4 v = *(const float4*)&g_vp[i*4];
        __half2 h2[2];
        h2[0] = __floats2half2_rn(v.x, v.y);
        h2[1] = __floats2half2_rn(v.z, v.w);
        *(uint2*)&g_vph[i*4] = *(uint2*)h2;
    }
}

// ---------------- coef: (B*S x 512) @ (512 x 80) ------------------------------
__global__ void coef_kernel(const float* __restrict__ bcoef)
{
    __shared__ float qsm[16*33];
    __shared__ float wsm[32*80];
    const int bm = blockIdx.x * 16;
    const int t = threadIdx.x;
    const int r = t & 15;             // row within tile
    const int cg = t >> 4;            // col group: 5 cols each (16 groups)
    float acc[5] = {};
    for (int k0 = 0; k0 < D; k0 += 32) {
        #pragma unroll
        for (int i = 0; i < 2; i++) {
            int idx = i*256 + t;
            int rr = idx >> 5, cc = idx & 31;
            qsm[rr*33 + cc] = g_qp[(size_t)(bm + rr) * D + k0 + cc];
        }
        #pragma unroll
        for (int i = 0; i < 3; i++) {
            int idx = i*256 + t;
            if (idx < 640)
                *(float4*)&wsm[idx*4] = *(const float4*)&g_wt[k0*80 + idx*4];
        }
        __syncthreads();
        #pragma unroll 8
        for (int kk = 0; kk < 32; kk++) {
            float a = qsm[r*33 + kk];
            #pragma unroll
            for (int j = 0; j < 5; j++)
                acc[j] += a * wsm[kk*80 + cg*5 + j];
        }
        __syncthreads();
    }
    const int rg = bm + r;
    const int b = rg >> 11, s = rg & (S-1);
    #pragma unroll
    for (int j = 0; j < 5; j++) {
        int nh = cg*5 + j;
        int n = nh >> 3, h = nh & 7;
        float v = acc[j] + bcoef[nh];
        if (n == 1) v = fabsf(v);
        g_coef[(((size_t)n*B + b)*H + h)*S + s] = 0.0125f * v;   // 0.1 / sqrt(64)
    }
}

// ---------------- basis ladder + 10-term dot (fp32) ---------------------------
__device__ __forceinline__ float basis_dot(float x, const float* cc)
{
    float t = fmaf(-2.f, rintf(0.5f * x), x);        // period-2 reduction
    float s1, c1;
    __sincosf(PI_F * t, &s1, &c1);
    float t2 = 2.f * fmaf(-2.f*s1, s1, 1.f);         // 2*cos(2 pi x)
    float s3 = fmaf(t2, s1,  s1),  c3 = fmaf(t2, c1, -c1);
    float s5 = fmaf(t2, s3, -s1),  c5 = fmaf(t2, c3, -c1);
    float s7 = fmaf(t2, s5, -s3),  c7 = fmaf(t2, c5, -c3);
    float s9 = fmaf(t2, s7, -s5),  c9 = fmaf(t2, c7, -c5);
    float a = cc[0] * x;
    a = fmaf(cc[1], x*x, a);                         // cc[1] pre-scaled by -0.5
    a = fmaf(cc[2], s1, a);  a = fmaf(cc[3], c1, a);
    a = fmaf(cc[4], s3, a);  a = fmaf(cc[5], c3, a);
    a = fmaf(cc[6], s5, a);  a = fmaf(cc[7], c5, a);
    a = fmaf(cc[8], s9, a);  a = fmaf(cc[9], c9, a);
    return a;
}

// ---------------- fused basis + QK^T (PTX mma) + exp + rowsum ----------------
// One head per block, 64q x 64k. Basis dot written straight into mma C frags.
#define QK_LD 72
#define ET_LD 68
__global__ __launch_bounds__(256) void logits_kernel(const float* __restrict__ xdiff)
{
    __shared__ __half qs[64*QK_LD];
    __shared__ __half ks[64*QK_LD];

    const int bh = blockIdx.x, b = bh >> 3, h = bh & 7;
    const int k0 = blockIdx.y * 64, q0 = blockIdx.z * 64;
    const int tid = threadIdx.x;
    const int w = tid >> 5, lane = tid & 31;
    const int wr = w >> 1, wc = w & 1;        // 4x2 warps; warp tile 16q x 32k

    // tile loads (issue early; latency covered by basis compute below)
    for (int idx = tid; idx < 64*16; idx += 256) {
        int q = idx >> 4, c = (idx & 15) * 4;
        *(uint2*)&qs[q*QK_LD + c] =
            *(const uint2*)&g_qph[((size_t)b*S + q0 + q) * D + h*DH + c];
    }
    for (int idx = tid; idx < 64*16; idx += 256) {
        int k = idx >> 4, c = (idx & 15) * 4;
        *(uint2*)&ks[k*QK_LD + c] =
            *(const uint2*)&g_kph[((size_t)b*S + k0 + k) * D + h*DH + c];
    }

    // thread's cells per mma.m16n8k16 C layout:
    //   rows qr, qr+8 ; cols kc0 + j*8 + {0,1}, j = 0..3
    const int qr  = wr*16 + (lane >> 2);
    const int kc0 = wc*32 + (lane & 3)*2;

    float c[4][4];
    #pragma unroll
    for (int jr = 0; jr < 2; jr++) {
        const int row = qr + jr*8;
        float cc[10];
        #pragma unroll
        for (int n = 0; n < NB; n++)
            cc[n] = __ldg(&g_coef[(((size_t)n*B + b)*H + h)*S + q0 + row]);
        cc[1] = -0.5f * cc[1];
        const float* xrow = &xdiff[((size_t)b*S + q0 + row) * S + k0];
        #pragma unroll
        for (int j = 0; j < 4; j++) {
            float2 x2 = *(const float2*)&xrow[kc0 + j*8];
            c[j][jr*2 + 0] = basis_dot(x2.x, cc);
            c[j][jr*2 + 1] = basis_dot(x2.y, cc);
        }
    }
    __syncthreads();

    // mma: c += (0.125*Q) K^T   (fp16 inputs, fp32 accum)
    #pragma unroll
    for (int kk = 0; kk < 4; kk++) {
        u32 a0, a1, a2, a3;
        ldsm4(a0, a1, a2, a3,
              sptr(&qs[(wr*16 + (lane & 15))*QK_LD + kk*16 + (lane >> 4)*8]));
        #pragma unroll
        for (int jj = 0; jj < 2; jj++) {
            u32 b0, b1, b2, b3;
            ldsm4(b0, b1, b2, b3,
                  sptr(&ks[(wc*32 + jj*16 + (lane & 7) + ((lane >> 4) & 1)*8)*QK_LD
                           + kk*16 + ((lane >> 3) & 1)*8]));
            mma16816(c[jj*2],     a0, a1, a2, a3, b0, b1);
            mma16816(c[jj*2 + 1], a0, a1, a2, a3, b2, b3);
        }
    }

    // exp in registers + row partial sums
    float s0 = 0.f, s1 = 0.f;
    #pragma unroll
    for (int j = 0; j < 4; j++) {
        c[j][0] = __expf(c[j][0]); c[j][1] = __expf(c[j][1]);
        c[j][2] = __expf(c[j][2]); c[j][3] = __expf(c[j][3]);
        s0 += c[j][0] + c[j][1];
        s1 += c[j][2] + c[j][3];
    }
    s0 += __shfl_xor_sync(0xffffffffu, s0, 1);
    s0 += __shfl_xor_sync(0xffffffffu, s0, 2);
    s1 += __shfl_xor_sync(0xffffffffu, s1, 1);
    s1 += __shfl_xor_sync(0xffffffffu, s1, 2);
    if ((lane & 3) == 0) {
        atomicAdd(&g_rowsum[(size_t)bh*S + q0 + qr],     s0);
        atomicAdd(&g_rowsum[(size_t)bh*S + q0 + qr + 8], s1);
    }

    __syncthreads();              // all warps done reading qs
    __half* et = qs;              // reuse qs as 64 x ET_LD half staging
    #pragma unroll
    for (int j = 0; j < 4; j++) {
        int kc = kc0 + j*8;
        *(__half2*)&et[qr*ET_LD + kc]       = __floats2half2_rn(c[j][0], c[j][1]);
        *(__half2*)&et[(qr + 8)*ET_LD + kc] = __floats2half2_rn(c[j][2], c[j][3]);
    }
    __syncthreads();

    // coalesced e store
    for (int idx = tid; idx < 64*16; idx += 256) {
        int row = idx >> 4, c4 = (idx & 15) * 4;
        *(uint2*)&g_e[((size_t)bh*S + q0 + row) * S + k0 + c4] =
            *(const uint2*)&et[row*ET_LD + c4];
    }
}

// ---------------- fused normalize + PV (fp16 wmma, single pass) --------------
#define SPH_LD 72
__global__ __launch_bounds__(256) void softpv_kernel(float* __restrict__ attn)
{
    __shared__ __half pt[64*SPH_LD];
    __shared__ __half vt[64*SPH_LD];
    const int b = blockIdx.z, h = blockIdx.y;
    const int q0 = blockIdx.x * 64;
    const int tid = threadIdx.x;
    const int r  = tid >> 2, tq = tid & 3;    // 64 rows x 4 threads
    const int w = tid >> 5;
    const int wr = w >> 1, wc = w & 1;        // 4x2 warps: 16q x 32d each

    const size_t rowbase = ((size_t)(b*H + h)*S + q0) * S;
    const __half* erow = g_e + rowbase + (size_t)r * S;
    const float riz = 1.f / g_rowsum[(size_t)(b*H + h)*S + q0 + r];

    wmma::fragment<wmma::accumulator, 16,16,16, float> acc[2];
    wmma::fill_fragment(acc[0], 0.f);
    wmma::fill_fragment(acc[1], 0.f);

    float* arow = attn + rowbase + (size_t)r * S;
    for (int k0 = 0; k0 < S; k0 += 64) {
        #pragma unroll
        for (int i = 0; i < 4; i++) {
            int idx = i*256 + tid;                    // uint2 (4 halves) units
            int k = idx >> 4, c = (idx & 15) * 4;
            *(uint2*)&vt[k*SPH_LD + c] =
                *(const uint2*)&g_vph[((size_t)b*S + k0 + k)*D + h*DH + c];
        }
        {
            const __half2* ep = (const __half2*)(erow + k0 + tq*16);
            #pragma unroll
            for (int j = 0; j < 4; j++) {
                __half2 e0 = ep[2*j], e1 = ep[2*j+1];
                float2 f0 = __half22float2(e0), f1 = __half22float2(e1);
                f0.x *= riz; f0.y *= riz; f1.x *= riz; f1.y *= riz;
                *(float4*)&arow[k0 + tq*16 + j*4] = make_float4(f0.x, f0.y, f1.x, f1.y);
                __half2 h2[2];
                h2[0] = __floats2half2_rn(f0.x, f0.y);
                h2[1] = __floats2half2_rn(f1.x, f1.y);
                *(uint2*)&pt[r*SPH_LD + tq*16 + j*4] = *(uint2*)h2;
            }
        }
        __syncthreads();
        #pragma unroll
        for (int ch = 0; ch < 4; ch++) {
            wmma::fragment<wmma::matrix_a, 16,16,16, __half, wmma::row_major> af;
            wmma::load_matrix_sync(af, pt + wr*16*SPH_LD + ch*16, SPH_LD);
            #pragma unroll
            for (int nb = 0; nb < 2; nb++) {
                wmma::fragment<wmma::matrix_b, 16,16,16, __half, wmma::row_major> bf;
                wmma::load_matrix_sync(bf, vt + (ch*16)*SPH_LD + wc*32 + nb*16, SPH_LD);
                wmma::mma_sync(acc[nb], af, bf, acc[nb]);
            }
        }
        __syncthreads();
    }
    #pragma unroll
    for (int nb = 0; nb < 2; nb++) {
        float* o = &g_attnv[((size_t)b*S + q0 + wr*16)*D + h*DH + wc*32 + nb*16];
        wmma::store_matrix_sync(o, acc[nb], D, wmma::mem_row_major);
    }
}

// -----------------------------------------------------------------------------
extern "C" void kernel_launch(void* const* d_in, const int* in_sizes, int n_in,
                              void* d_out, int out_size)
{
    const float* q     = (const float*)d_in[0];
    const float* k     = (const float*)d_in[1];
    const float* v     = (const float*)d_in[2];
    const float* xdiff = (const float*)d_in[3];
    const float* Wq    = (const float*)d_in[4];
    const float* bq    = (const float*)d_in[5];
    const float* Wk    = (const float*)d_in[6];
    const float* bk    = (const float*)d_in[7];
    const float* Wv    = (const float*)d_in[8];
    const float* bv    = (const float*)d_in[9];
    const float* Wcoef = (const float*)d_in[10];
    const float* bcoef = (const float*)d_in[11];
    const float* Wo    = (const float*)d_in[12];
    const float* bo    = (const float*)d_in[13];
    float* out = (float*)d_out;                       // [B*S*D] out | [B*H*S*S] attn
    float* attn = out + (size_t)B*S*D;

    float *qp, *kp, *vp, *av, *rs;
    cudaGetSymbolAddress((void**)&qp, g_qp);
    cudaGetSymbolAddress((void**)&kp, g_kp);
    cudaGetSymbolAddress((void**)&vp, g_vp);
    cudaGetSymbolAddress((void**)&av, g_attnv);
    cudaGetSymbolAddress((void**)&rs, g_rowsum);

    cudaMemsetAsync(rs, 0, (size_t)B*H*S*sizeof(float), 0);

    dim3 ggrid(D/64, (B*S)/128);
    gemm_bias_tc<<<ggrid, 256>>>(q, Wq, bq, qp, B*S, D, D);
    gemm_bias_tc<<<ggrid, 256>>>(k, Wk, bk, kp, B*S, D, D);
    gemm_bias_tc<<<ggrid, 256>>>(v, Wv, bv, vp, B*S, D, D);

    transw_kernel<<<(D*NB*H + 255)/256, 256>>>(Wcoef);
    qkvconv_kernel<<<(B*S*D/4)/256, 256>>>();
    coef_kernel<<<(B*S)/16, 256>>>(bcoef);

    logits_kernel<<<dim3(B*H, S/64, S/64), 256>>>(xdiff);

    softpv_kernel<<<dim3(S/64, H, B), 256>>>(attn);

    gemm_bias_tc<<<ggrid, 256>>>(av, Wo, bo, out, B*S, D, D);
}